// round 6
// baseline (speedup 1.0000x reference)
#include <cuda_runtime.h>
#include <cuda_bf16.h>
#include <math.h>

#define Nn 10000
#define Hh 512
#define Tt 4
#define Ee 40000
#define Ll 2
#define G3 (3*Hh)
#define TN (Tt*Nn)
#define WMSG_SZ (Ll*Tt*Hh*Hh)
#define WIH_SZ  (Ll*G3*Hh)
#define FC_SZ   (Hh*Hh)

typedef unsigned long long u64;
typedef unsigned int u32;
typedef __nv_bfloat16 bf;

// ---------------- device scratch ----------------
__device__ __align__(16) float g_h  [2*(size_t)Nn*Hh];
__device__ __align__(16) float g_gi [(size_t)Nn*G3];
__device__ __align__(16) float g_gh [(size_t)Nn*G3];
__device__ __align__(16) float g_pm [100*Hh];
// bf16 hi/lo operand buffers
__device__ __align__(16) bf g_Shi[(size_t)TN*Hh];
__device__ __align__(16) bf g_Slo[(size_t)TN*Hh];
__device__ __align__(16) bf g_ihi[(size_t)Nn*Hh];
__device__ __align__(16) bf g_ilo[(size_t)Nn*Hh];
__device__ __align__(16) bf g_hhi[(size_t)Nn*Hh];
__device__ __align__(16) bf g_hlo[(size_t)Nn*Hh];
__device__ __align__(16) bf g_Wmh[WMSG_SZ];
__device__ __align__(16) bf g_Wml[WMSG_SZ];
__device__ __align__(16) bf g_Wih[WIH_SZ];
__device__ __align__(16) bf g_Wil[WIH_SZ];
__device__ __align__(16) bf g_Whh[WIH_SZ];
__device__ __align__(16) bf g_Whl[WIH_SZ];
__device__ __align__(16) bf g_fch[FC_SZ];
__device__ __align__(16) bf g_fcl[FC_SZ];
// CSR
__device__ int g_deg [TN];
__device__ int g_off [TN + 1];
__device__ int g_cur [TN];
__device__ int g_csr [Tt*Ee];
__device__ int g_bsum[64];
__device__ int g_bofs[64];

// ---------------- smem geometry (padded bf16 rows) ----------------
#define LDSB  80
#define ATILE 10240
#define BUFSZ (4*ATILE)
#define SMEM_BYTES (2*BUFSZ)

__device__ __forceinline__ u32 smem_u32(const void* p) {
    u32 a;
    asm("{ .reg .u64 t; cvta.to.shared.u64 t, %1; cvt.u32.u64 %0, t; }" : "=r"(a) : "l"(p));
    return a;
}
__device__ __forceinline__ void ldsm4(u32 r[4], u32 addr) {
    asm volatile("ldmatrix.sync.aligned.m8n8.x4.shared.b16 {%0,%1,%2,%3}, [%4];"
                 : "=r"(r[0]), "=r"(r[1]), "=r"(r[2]), "=r"(r[3]) : "r"(addr));
}
__device__ __forceinline__ void mma16816(float d[4], const u32 a[4], u32 b0, u32 b1) {
    asm volatile("mma.sync.aligned.m16n8k16.row.col.f32.bf16.bf16.f32 "
                 "{%0,%1,%2,%3}, {%4,%5,%6,%7}, {%8,%9}, {%0,%1,%2,%3};"
                 : "+f"(d[0]), "+f"(d[1]), "+f"(d[2]), "+f"(d[3])
                 : "r"(a[0]), "r"(a[1]), "r"(a[2]), "r"(a[3]), "r"(b0), "r"(b1));
}
__device__ __forceinline__ void split1(float v, bf& h, bf& l) {
    h = __float2bfloat16(v);
    l = __float2bfloat16(v - __bfloat162float(h));
}

// ---- bf16 tile loaders: 128 rows x 32 cols, 2 uint4 per thread per array ----
__device__ __forceinline__ void ldg_bf(const bf* __restrict__ base, int rowMax,
                                       int r0, int tid, uint4 r[2]) {
#pragma unroll
    for (int i = 0; i < 2; i++) {
        int c = i * 256 + tid;
        int row = c >> 2, chunk = c & 3;
        int m = r0 + row;
        if (m < rowMax)
            r[i] = *reinterpret_cast<const uint4*>(base + (size_t)m * Hh + chunk * 8);
        else
            r[i] = make_uint4(0u, 0u, 0u, 0u);
    }
}
__device__ __forceinline__ void sts_bf(char* dst, int tid, const uint4 r[2]) {
#pragma unroll
    for (int i = 0; i < 2; i++) {
        int c = i * 256 + tid;
        int row = c >> 2, chunk = c & 3;
        *reinterpret_cast<uint4*>(dst + row * LDSB + chunk * 16) = r[i];
    }
}

// ============ bf16 3-split HMMA GEMM, pre-split operands (2 CTAs/SM) ============
__global__ __launch_bounds__(256, 2)
void mma_gemm(const bf* __restrict__ Ahi, const bf* __restrict__ Alo,
              const bf* __restrict__ Bhi, const bf* __restrict__ Blo,
              const float* __restrict__ bias, const float* __restrict__ bm,
              const int* __restrict__ deg,
              float* __restrict__ C, bf* __restrict__ outHi, bf* __restrict__ outLo,
              int M, int Nout, int nSeg)
{
    extern __shared__ __align__(16) char smem[];
    const int tid = threadIdx.x;
    const int lane = tid & 31, wid = tid >> 5;
    const int wm = wid & 3, wn = wid >> 2;
    const int m0 = blockIdx.x * 128, n0 = blockIdx.y * 128;
    const int NKB = nSeg * 16;
    const bool msg = (nSeg > 1);
    u32 sb = smem_u32(smem);

    float acc[2][8][4];
#pragma unroll
    for (int i = 0; i < 2; i++)
#pragma unroll
        for (int j = 0; j < 8; j++)
#pragma unroll
            for (int k = 0; k < 4; k++) acc[i][j][k] = 0.f;

    // prologue: k-block 0 into buffer 0
    {
        uint4 rAh[2], rAl[2], rBh[2], rBl[2];
        ldg_bf(Ahi, M, m0, tid, rAh);
        ldg_bf(Alo, M, m0, tid, rAl);
        ldg_bf(Bhi, 1 << 30, n0, tid, rBh);
        ldg_bf(Blo, 1 << 30, n0, tid, rBl);
        sts_bf(smem, tid, rAh);
        sts_bf(smem + ATILE, tid, rAl);
        sts_bf(smem + 2 * ATILE, tid, rBh);
        sts_bf(smem + 3 * ATILE, tid, rBl);
    }
    __syncthreads();

    for (int kb = 0; kb < NKB; kb++) {
        int buf = kb & 1;
        if (kb + 1 < NKB) {
            uint4 rAh[2], rAl[2], rBh[2], rBl[2];
            int kn = kb + 1;
            int tseg = kn >> 4, koff = (kn & 15) * 32;
            size_t ao = (size_t)tseg * ((size_t)Nn * Hh) + koff;
            size_t bo = (size_t)tseg * ((size_t)Hh * Hh) + koff;
            ldg_bf(Ahi + ao, M, m0, tid, rAh);
            ldg_bf(Alo + ao, M, m0, tid, rAl);
            ldg_bf(Bhi + bo, 1 << 30, n0, tid, rBh);
            ldg_bf(Blo + bo, 1 << 30, n0, tid, rBl);
            char* dst = smem + (kn & 1) * BUFSZ;
            sts_bf(dst, tid, rAh);
            sts_bf(dst + ATILE, tid, rAl);
            sts_bf(dst + 2 * ATILE, tid, rBh);
            sts_bf(dst + 3 * ATILE, tid, rBl);
        }
        u32 aHi = sb + buf * BUFSZ;
        u32 aLo = aHi + ATILE, bHi = aHi + 2 * ATILE, bLo = aHi + 3 * ATILE;
#pragma unroll
        for (int ks = 0; ks < 2; ks++) {
            u32 ah[2][4], al[2][4];
#pragma unroll
            for (int mt = 0; mt < 2; mt++) {
                u32 ro = (u32)((wm * 32 + mt * 16 + (lane & 15)) * LDSB
                               + (ks * 16 + (lane >> 4) * 8) * 2);
                ldsm4(ah[mt], aHi + ro);
                ldsm4(al[mt], aLo + ro);
            }
#pragma unroll
            for (int half = 0; half < 2; half++) {
                u32 bh[2][4], bl[2][4];
#pragma unroll
                for (int np = 0; np < 2; np++) {
                    int np2 = half * 2 + np;
                    u32 ro = (u32)((wn * 64 + np2 * 16 + (lane & 7) + ((lane >> 3) & 1) * 8) * LDSB
                                   + (ks * 16 + (lane >> 4) * 8) * 2);
                    ldsm4(bh[np], bHi + ro);
                    ldsm4(bl[np], bLo + ro);
                }
#pragma unroll
                for (int mt = 0; mt < 2; mt++)
#pragma unroll
                    for (int j = 0; j < 4; j++) {
                        int np = j >> 1, sub = j & 1;
                        int nt = half * 4 + j;
                        mma16816(acc[mt][nt], ah[mt], bh[np][sub], bh[np][sub + 2]);
                        mma16816(acc[mt][nt], ah[mt], bl[np][sub], bl[np][sub + 2]);
                        mma16816(acc[mt][nt], al[mt], bh[np][sub], bh[np][sub + 2]);
                    }
            }
        }
        __syncthreads();
    }

    // ---- epilogue ----
#pragma unroll
    for (int mt = 0; mt < 2; mt++) {
        int rbase = m0 + wm * 32 + mt * 16 + (lane >> 2);
#pragma unroll
        for (int half = 0; half < 2; half++) {
            int r = rbase + half * 8;
            if (r >= M) continue;
            float dgv[Tt];
            if (msg) {
#pragma unroll
                for (int t = 0; t < Tt; t++) dgv[t] = (float)deg[t * Nn + r];
            }
#pragma unroll
            for (int nt = 0; nt < 8; nt++) {
                int col = n0 + wn * 64 + nt * 8 + (lane & 3) * 2;
                float v0 = acc[mt][nt][half * 2 + 0];
                float v1 = acc[mt][nt][half * 2 + 1];
                if (msg) {
#pragma unroll
                    for (int t = 0; t < Tt; t++) {
                        float2 b = *reinterpret_cast<const float2*>(bm + t * Hh + col);
                        v0 += dgv[t] * b.x;
                        v1 += dgv[t] * b.y;
                    }
                } else {
                    float2 b = *reinterpret_cast<const float2*>(bias + col);
                    v0 += b.x; v1 += b.y;
                }
                if (outHi) {
                    bf h0, l0, h1, l1;
                    split1(v0, h0, l0);
                    split1(v1, h1, l1);
                    size_t o = (size_t)r * Nout + col;
                    *reinterpret_cast<__nv_bfloat162*>(outHi + o) = __nv_bfloat162(h0, h1);
                    *reinterpret_cast<__nv_bfloat162*>(outLo + o) = __nv_bfloat162(l0, l1);
                } else {
                    *reinterpret_cast<float2*>(C + (size_t)r * Nout + col) = make_float2(v0, v1);
                }
            }
        }
    }
}

// ---------------- utility / conversion kernels ----------------
__global__ void copy_f4(const float4* __restrict__ s, float4* __restrict__ d, int n4) {
    int i = blockIdx.x * blockDim.x + threadIdx.x;
    int stride = gridDim.x * blockDim.x;
    for (; i < n4; i += stride) d[i] = s[i];
}
__global__ void cvt_split(const float* __restrict__ in, bf* __restrict__ hi,
                          bf* __restrict__ lo, int n4) {
    int i = blockIdx.x * blockDim.x + threadIdx.x;
    int stride = gridDim.x * blockDim.x;
    for (; i < n4; i += stride) {
        float4 v = reinterpret_cast<const float4*>(in)[i];
        bf h0,l0,h1,l1,h2,l2,h3,l3;
        split1(v.x, h0, l0); split1(v.y, h1, l1);
        split1(v.z, h2, l2); split1(v.w, h3, l3);
        *reinterpret_cast<__nv_bfloat162*>(hi + i*4)     = __nv_bfloat162(h0, h1);
        *reinterpret_cast<__nv_bfloat162*>(hi + i*4 + 2) = __nv_bfloat162(h2, h3);
        *reinterpret_cast<__nv_bfloat162*>(lo + i*4)     = __nv_bfloat162(l0, l1);
        *reinterpret_cast<__nv_bfloat162*>(lo + i*4 + 2) = __nv_bfloat162(l2, l3);
    }
}
__global__ void zero_i(int* p, int n) {
    int i = blockIdx.x * blockDim.x + threadIdx.x;
    if (i < n) p[i] = 0;
}
__global__ void count_deg(const int* __restrict__ edges, int* __restrict__ deg) {
    int idx = blockIdx.x * blockDim.x + threadIdx.x;
    if (idx < Tt * Ee) {
        int t = idx / Ee;
        int tgt = edges[idx * 2 + 1];
        atomicAdd(&deg[t * Nn + tgt], 1);
    }
}

// ---------------- CSR build ----------------
__global__ void scan1(const int* __restrict__ deg, int* __restrict__ off, int* __restrict__ bsum) {
    __shared__ int sm[1024];
    int t = threadIdx.x;
    int i = blockIdx.x * 1024 + t;
    int v = (i < TN) ? deg[i] : 0;
    sm[t] = v;
    __syncthreads();
    for (int d = 1; d < 1024; d <<= 1) {
        int x = (t >= d) ? sm[t - d] : 0;
        __syncthreads();
        sm[t] += x;
        __syncthreads();
    }
    if (i < TN) off[i + 1] = sm[t];
    if (t == 1023) bsum[blockIdx.x] = sm[t];
}
__global__ void scan2(const int* __restrict__ bsum, int* __restrict__ bofs, int nb) {
    __shared__ int sm[64];
    int t = threadIdx.x;
    int v = (t < nb) ? bsum[t] : 0;
    sm[t] = v;
    __syncthreads();
    for (int d = 1; d < 64; d <<= 1) {
        int x = (t >= d) ? sm[t - d] : 0;
        __syncthreads();
        sm[t] += x;
        __syncthreads();
    }
    bofs[t] = sm[t] - v;
}
__global__ void scan3(int* __restrict__ off, const int* __restrict__ bofs) {
    int i = blockIdx.x * blockDim.x + threadIdx.x;
    if (i == 0) off[0] = 0;
    if (i < TN) off[i + 1] += bofs[i >> 10];
}
__global__ void scatter_csr(const int* __restrict__ edges, const int* __restrict__ off,
                            int* __restrict__ cur, int* __restrict__ csr) {
    int idx = blockIdx.x * blockDim.x + threadIdx.x;
    if (idx >= Tt * Ee) return;
    int t = idx / Ee;
    int src = edges[idx * 2 + 0];
    int tgt = edges[idx * 2 + 1];
    int r = t * Nn + tgt;
    int p = off[r] + atomicAdd(&cur[r], 1);
    csr[p] = src;
}

// ---------------- CSR aggregation -> bf16 hi/lo S ----------------
__device__ __forceinline__ void st4_split(bf* hi, bf* lo, float4 a) {
    bf h0,l0,h1,l1,h2,l2,h3,l3;
    split1(a.x, h0, l0); split1(a.y, h1, l1);
    split1(a.z, h2, l2); split1(a.w, h3, l3);
    *reinterpret_cast<__nv_bfloat162*>(hi)     = __nv_bfloat162(h0, h1);
    *reinterpret_cast<__nv_bfloat162*>(hi + 2) = __nv_bfloat162(h2, h3);
    *reinterpret_cast<__nv_bfloat162*>(lo)     = __nv_bfloat162(l0, l1);
    *reinterpret_cast<__nv_bfloat162*>(lo + 2) = __nv_bfloat162(l2, l3);
}
__global__ void agg_csr(const float* __restrict__ h, const int* __restrict__ csr,
                        const int* __restrict__ off, bf* __restrict__ Shi,
                        bf* __restrict__ Slo) {
    int row = (blockIdx.x * blockDim.x + threadIdx.x) >> 5;
    int lane = threadIdx.x & 31;
    if (row >= TN) return;
    int s = off[row], e = off[row + 1];
    float4 a0 = make_float4(0.f,0.f,0.f,0.f), a1 = a0, a2 = a0, a3 = a0;
    for (int i = s; i < e; i++) {
        int src = __ldg(csr + i);
        const float4* hp = reinterpret_cast<const float4*>(h + (size_t)src * Hh);
        float4 v0 = hp[lane], v1 = hp[lane + 32], v2 = hp[lane + 64], v3 = hp[lane + 96];
        a0.x += v0.x; a0.y += v0.y; a0.z += v0.z; a0.w += v0.w;
        a1.x += v1.x; a1.y += v1.y; a1.z += v1.z; a1.w += v1.w;
        a2.x += v2.x; a2.y += v2.y; a2.z += v2.z; a2.w += v2.w;
        a3.x += v3.x; a3.y += v3.y; a3.z += v3.z; a3.w += v3.w;
    }
    bf* Hp = Shi + (size_t)row * Hh;
    bf* Lp = Slo + (size_t)row * Hh;
    st4_split(Hp + lane * 4,         Lp + lane * 4,         a0);
    st4_split(Hp + (lane + 32) * 4,  Lp + (lane + 32) * 4,  a1);
    st4_split(Hp + (lane + 64) * 4,  Lp + (lane + 64) * 4,  a2);
    st4_split(Hp + (lane + 96) * 4,  Lp + (lane + 96) * 4,  a3);
}

// ---------------- GRU elementwise (writes fp32 h + bf16 hi/lo h) ----------------
__global__ void gru_kernel(const float* __restrict__ gi, const float* __restrict__ gh,
                           const float* __restrict__ h, float* __restrict__ hout,
                           bf* __restrict__ hhi, bf* __restrict__ hlo) {
    int idx = blockIdx.x * blockDim.x + threadIdx.x;
    if (idx >= Nn * Hh) return;
    int n = idx / Hh;
    int j = idx - n * Hh;
    size_t base = (size_t)n * G3 + j;
    float ir = gi[base],          hr = gh[base];
    float iz = gi[base + Hh],     hz = gh[base + Hh];
    float in_ = gi[base + 2*Hh],  hn = gh[base + 2*Hh];
    float r = 1.f / (1.f + expf(-(ir + hr)));
    float z = 1.f / (1.f + expf(-(iz + hz)));
    float nv = tanhf(in_ + r * hn);
    float hv = (1.f - z) * nv + z * h[idx];
    hout[idx] = hv;
    bf hb, lb;
    split1(hv, hb, lb);
    hhi[idx] = hb;
    hlo[idx] = lb;
}

// ---------------- column max ----------------
__global__ void pmax_kernel(const float* __restrict__ X, float* __restrict__ pm) {
    int k = threadIdx.x;
    int b = blockIdx.x;
    float m = -INFINITY;
    int r0 = b * 100;
    for (int r = 0; r < 100; r++)
        m = fmaxf(m, X[(size_t)(r0 + r) * Hh + k]);
    pm[b * Hh + k] = m;
}
__global__ void fmax_kernel(const float* __restrict__ pm, float* __restrict__ out) {
    int k = threadIdx.x;
    float m = -INFINITY;
    for (int b = 0; b < 100; b++)
        m = fmaxf(m, pm[b * Hh + k]);
    out[k] = m;
}

// ---------------- launch ----------------
extern "C" void kernel_launch(void* const* d_in, const int* in_sizes, int n_in,
                              void* d_out, int out_size) {
    const float* x     = (const float*)d_in[0];
    const int*   edges = (const int*)  d_in[1];
    const float* W_msg = (const float*)d_in[2];
    const float* b_msg = (const float*)d_in[3];
    const float* W_ih  = (const float*)d_in[4];
    const float* W_hh  = (const float*)d_in[5];
    const float* b_ih  = (const float*)d_in[6];
    const float* b_hh  = (const float*)d_in[7];
    const float* fc_W  = (const float*)d_in[8];
    const float* fc_b  = (const float*)d_in[9];
    float* out = (float*)d_out;

    float *ph, *pgi, *pgh, *ppm;
    bf *pShi, *pSlo, *pihi, *pilo, *phhi, *phlo;
    bf *pWmh, *pWml, *pWih, *pWil, *pWhh, *pWhl, *pfch, *pfcl;
    int *pdeg, *poff, *pcur, *pcsr, *pbsum, *pbofs;
    cudaGetSymbolAddress((void**)&ph,    g_h);
    cudaGetSymbolAddress((void**)&pgi,   g_gi);
    cudaGetSymbolAddress((void**)&pgh,   g_gh);
    cudaGetSymbolAddress((void**)&ppm,   g_pm);
    cudaGetSymbolAddress((void**)&pShi,  g_Shi);
    cudaGetSymbolAddress((void**)&pSlo,  g_Slo);
    cudaGetSymbolAddress((void**)&pihi,  g_ihi);
    cudaGetSymbolAddress((void**)&pilo,  g_ilo);
    cudaGetSymbolAddress((void**)&phhi,  g_hhi);
    cudaGetSymbolAddress((void**)&phlo,  g_hlo);
    cudaGetSymbolAddress((void**)&pWmh,  g_Wmh);
    cudaGetSymbolAddress((void**)&pWml,  g_Wml);
    cudaGetSymbolAddress((void**)&pWih,  g_Wih);
    cudaGetSymbolAddress((void**)&pWil,  g_Wil);
    cudaGetSymbolAddress((void**)&pWhh,  g_Whh);
    cudaGetSymbolAddress((void**)&pWhl,  g_Whl);
    cudaGetSymbolAddress((void**)&pfch,  g_fch);
    cudaGetSymbolAddress((void**)&pfcl,  g_fcl);
    cudaGetSymbolAddress((void**)&pdeg,  g_deg);
    cudaGetSymbolAddress((void**)&poff,  g_off);
    cudaGetSymbolAddress((void**)&pcur,  g_cur);
    cudaGetSymbolAddress((void**)&pcsr,  g_csr);
    cudaGetSymbolAddress((void**)&pbsum, g_bsum);
    cudaGetSymbolAddress((void**)&pbofs, g_bofs);

    cudaFuncSetAttribute(mma_gemm, cudaFuncAttributeMaxDynamicSharedMemorySize, SMEM_BYTES);

    float* hc = ph;
    float* hn = ph + (size_t)Nn * Hh;

    // init: h=x (fp32 + bf16 split), weight splits, CSR
    copy_f4<<<2048, 256>>>((const float4*)x, (float4*)hc, Nn * Hh / 4);
    cvt_split<<<2048, 256>>>(x, phhi, phlo, Nn * Hh / 4);
    cvt_split<<<2048, 256>>>(W_msg, pWmh, pWml, WMSG_SZ / 4);
    cvt_split<<<2048, 256>>>(W_ih,  pWih, pWil, WIH_SZ / 4);
    cvt_split<<<2048, 256>>>(W_hh,  pWhh, pWhl, WIH_SZ / 4);
    cvt_split<<<1024, 256>>>(fc_W,  pfch, pfcl, FC_SZ / 4);

    zero_i<<<(TN + 255) / 256, 256>>>(pdeg, TN);
    zero_i<<<(TN + 255) / 256, 256>>>(pcur, TN);
    count_deg<<<(Tt * Ee + 255) / 256, 256>>>(edges, pdeg);
    scan1<<<(TN + 1023) / 1024, 1024>>>(pdeg, poff, pbsum);
    scan2<<<1, 64>>>(pbsum, pbofs, (TN + 1023) / 1024);
    scan3<<<(TN + 255) / 256, 256>>>(poff, pbofs);
    scatter_csr<<<(Tt * Ee + 255) / 256, 256>>>(edges, poff, pcur, pcsr);

    dim3 gm((Nn + 127) / 128, Hh / 128);    // 79 x 4
    dim3 gg((Nn + 127) / 128, G3 / 128);    // 79 x 12
    int aggBlocks = (TN * 32 + 255) / 256;

    for (int layer = 0; layer < Ll; layer++) {
        const bf* Wmh_l = pWmh + (size_t)layer * Tt * Hh * Hh;
        const bf* Wml_l = pWml + (size_t)layer * Tt * Hh * Hh;
        const bf* Wih_l = pWih + (size_t)layer * G3 * Hh;
        const bf* Wil_l = pWil + (size_t)layer * G3 * Hh;
        const bf* Whh_l = pWhh + (size_t)layer * G3 * Hh;
        const bf* Whl_l = pWhl + (size_t)layer * G3 * Hh;
        const float* bm_l  = b_msg + (size_t)layer * Tt * Hh;
        const float* bih_l = b_ih  + (size_t)layer * G3;
        const float* bhh_l = b_hh  + (size_t)layer * G3;
        for (int s = 0; s < 2; s++) {
            agg_csr<<<aggBlocks, 256>>>(hc, pcsr, poff, pShi, pSlo);
            mma_gemm<<<gm, 256, SMEM_BYTES>>>(pShi, pSlo, Wmh_l, Wml_l,
                                              nullptr, bm_l, pdeg,
                                              nullptr, pihi, pilo, Nn, Hh, Tt);
            mma_gemm<<<gg, 256, SMEM_BYTES>>>(pihi, pilo, Wih_l, Wil_l,
                                              bih_l, nullptr, nullptr,
                                              pgi, nullptr, nullptr, Nn, G3, 1);
            mma_gemm<<<gg, 256, SMEM_BYTES>>>(phhi, phlo, Whh_l, Whl_l,
                                              bhh_l, nullptr, nullptr,
                                              pgh, nullptr, nullptr, Nn, G3, 1);
            gru_kernel<<<(Nn * Hh + 255) / 256, 256>>>(pgi, pgh, hc, hn, phhi, phlo);
            float* t = hc; hc = hn; hn = t;
        }
    }

    mma_gemm<<<gm, 256, SMEM_BYTES>>>(phhi, phlo, pfch, pfcl,
                                      fc_b, nullptr, nullptr,
                                      pgi, nullptr, nullptr, Nn, Hh, 1);
    pmax_kernel<<<100, 512>>>(pgi, ppm);
    fmax_kernel<<<1, 512>>>(ppm, out);
}

// round 7
// speedup vs baseline: 1.1421x; 1.1421x over previous
#include <cuda_runtime.h>
#include <cuda_bf16.h>
#include <math.h>

#define Nn 10000
#define Hh 512
#define Tt 4
#define Ee 40000
#define Ll 2
#define G3 (3*Hh)
#define TN (Tt*Nn)
#define WMSG_SZ (Ll*Tt*Hh*Hh)
#define WIH_SZ  (Ll*G3*Hh)
#define FC_SZ   (Hh*Hh)

typedef unsigned long long u64;
typedef unsigned int u32;
typedef __nv_bfloat16 bf;

// ---------------- device scratch ----------------
__device__ __align__(16) float g_h  [2*(size_t)Nn*Hh];
__device__ __align__(16) float g_gi [(size_t)Nn*G3];
__device__ __align__(16) float g_gh [(size_t)Nn*G3];
__device__ __align__(16) float g_pm [100*Hh];
// bf16 hi/lo operand buffers
__device__ __align__(16) bf g_Shi[(size_t)TN*Hh];
__device__ __align__(16) bf g_Slo[(size_t)TN*Hh];
__device__ __align__(16) bf g_ihi[(size_t)Nn*Hh];
__device__ __align__(16) bf g_ilo[(size_t)Nn*Hh];
__device__ __align__(16) bf g_hhi[(size_t)Nn*Hh];
__device__ __align__(16) bf g_hlo[(size_t)Nn*Hh];
__device__ __align__(16) bf g_Wmh[WMSG_SZ];
__device__ __align__(16) bf g_Wml[WMSG_SZ];
__device__ __align__(16) bf g_Wih[WIH_SZ];
__device__ __align__(16) bf g_Wil[WIH_SZ];
__device__ __align__(16) bf g_Whh[WIH_SZ];
__device__ __align__(16) bf g_Whl[WIH_SZ];
__device__ __align__(16) bf g_fch[FC_SZ];
__device__ __align__(16) bf g_fcl[FC_SZ];
// CSR
__device__ int g_deg [TN];
__device__ int g_off [TN + 1];
__device__ int g_cur [TN];
__device__ int g_csr [Tt*Ee];
__device__ int g_bsum[64];
__device__ int g_bofs[64];

// ---------------- smem geometry (padded bf16 rows) ----------------
#define LDSB  80
#define ATILE 10240
#define BUFSZ (4*ATILE)
#define SMEM_BYTES (2*BUFSZ)

__device__ __forceinline__ u32 smem_u32(const void* p) {
    u32 a;
    asm("{ .reg .u64 t; cvta.to.shared.u64 t, %1; cvt.u32.u64 %0, t; }" : "=r"(a) : "l"(p));
    return a;
}
__device__ __forceinline__ void ldsm4(u32 r[4], u32 addr) {
    asm volatile("ldmatrix.sync.aligned.m8n8.x4.shared.b16 {%0,%1,%2,%3}, [%4];"
                 : "=r"(r[0]), "=r"(r[1]), "=r"(r[2]), "=r"(r[3]) : "r"(addr));
}
__device__ __forceinline__ void mma16816(float d[4], const u32 a[4], u32 b0, u32 b1) {
    asm volatile("mma.sync.aligned.m16n8k16.row.col.f32.bf16.bf16.f32 "
                 "{%0,%1,%2,%3}, {%4,%5,%6,%7}, {%8,%9}, {%0,%1,%2,%3};"
                 : "+f"(d[0]), "+f"(d[1]), "+f"(d[2]), "+f"(d[3])
                 : "r"(a[0]), "r"(a[1]), "r"(a[2]), "r"(a[3]), "r"(b0), "r"(b1));
}
__device__ __forceinline__ void split1(float v, bf& h, bf& l) {
    h = __float2bfloat16(v);
    l = __float2bfloat16(v - __bfloat162float(h));
}
__device__ __forceinline__ void cpa16(u32 saddr, const void* g) {
    asm volatile("cp.async.cg.shared.global [%0], [%1], 16;" :: "r"(saddr), "l"(g) : "memory");
}
#define CPA_COMMIT() asm volatile("cp.async.commit_group;" ::: "memory")
#define CPA_WAIT0()  asm volatile("cp.async.wait_group 0;" ::: "memory")

// ---- cp.async tile loader: 128 rows x 32 bf16 cols, 2 x 16B per thread ----
__device__ __forceinline__ void cpa_tile(const bf* __restrict__ base, int rowMax,
                                         int r0, int tid, u32 sdst) {
#pragma unroll
    for (int i = 0; i < 2; i++) {
        int c = i * 256 + tid;
        int row = c >> 2, chunk = c & 3;
        int m = r0 + row;
        if (m >= rowMax) m = rowMax - 1;   // clamp: ghost rows never written out
        cpa16(sdst + row * LDSB + chunk * 16, base + (size_t)m * Hh + chunk * 8);
    }
}

// ============ bf16 3-split HMMA GEMM, cp.async pipeline (2 CTAs/SM) ============
__global__ __launch_bounds__(256, 2)
void mma_gemm(const bf* __restrict__ Ahi, const bf* __restrict__ Alo,
              const bf* __restrict__ Bhi, const bf* __restrict__ Blo,
              const float* __restrict__ bias, const float* __restrict__ bm,
              const int* __restrict__ deg,
              float* __restrict__ C, bf* __restrict__ outHi, bf* __restrict__ outLo,
              int M, int Nout, int nSeg)
{
    extern __shared__ __align__(16) char smem[];
    const int tid = threadIdx.x;
    const int lane = tid & 31, wid = tid >> 5;
    const int wm = wid & 3, wn = wid >> 2;
    const int m0 = blockIdx.x * 128, n0 = blockIdx.y * 128;
    const int NKB = nSeg * 16;
    const bool msg = (nSeg > 1);
    u32 sb = smem_u32(smem);

    float acc[2][8][4];
#pragma unroll
    for (int i = 0; i < 2; i++)
#pragma unroll
        for (int j = 0; j < 8; j++)
#pragma unroll
            for (int k = 0; k < 4; k++) acc[i][j][k] = 0.f;

    // prologue: issue k-block 0 into buffer 0
    cpa_tile(Ahi, M, m0, tid, sb);
    cpa_tile(Alo, M, m0, tid, sb + ATILE);
    cpa_tile(Bhi, 1 << 30, n0, tid, sb + 2 * ATILE);
    cpa_tile(Blo, 1 << 30, n0, tid, sb + 3 * ATILE);
    CPA_COMMIT();

    for (int kb = 0; kb < NKB; kb++) {
        int buf = kb & 1;
        CPA_WAIT0();
        __syncthreads();          // buf[kb] ready; all warps done reading buf[kb-1]

        if (kb + 1 < NKB) {       // prefetch kb+1 into the other buffer; flies under MMA
            int kn = kb + 1;
            int tseg = kn >> 4, koff = (kn & 15) * 32;
            size_t ao = (size_t)tseg * ((size_t)Nn * Hh) + koff;
            size_t bo = (size_t)tseg * ((size_t)Hh * Hh) + koff;
            u32 dst = sb + (kn & 1) * BUFSZ;
            cpa_tile(Ahi + ao, M, m0, tid, dst);
            cpa_tile(Alo + ao, M, m0, tid, dst + ATILE);
            cpa_tile(Bhi + bo, 1 << 30, n0, tid, dst + 2 * ATILE);
            cpa_tile(Blo + bo, 1 << 30, n0, tid, dst + 3 * ATILE);
            CPA_COMMIT();
        }

        u32 aHi = sb + buf * BUFSZ;
        u32 aLo = aHi + ATILE, bHi = aHi + 2 * ATILE, bLo = aHi + 3 * ATILE;
#pragma unroll
        for (int ks = 0; ks < 2; ks++) {
            u32 ah[2][4], al[2][4];
#pragma unroll
            for (int mt = 0; mt < 2; mt++) {
                u32 ro = (u32)((wm * 32 + mt * 16 + (lane & 15)) * LDSB
                               + (ks * 16 + (lane >> 4) * 8) * 2);
                ldsm4(ah[mt], aHi + ro);
                ldsm4(al[mt], aLo + ro);
            }
#pragma unroll
            for (int half = 0; half < 2; half++) {
                u32 bh[2][4], bl[2][4];
#pragma unroll
                for (int np = 0; np < 2; np++) {
                    int np2 = half * 2 + np;
                    u32 ro = (u32)((wn * 64 + np2 * 16 + (lane & 7) + ((lane >> 3) & 1) * 8) * LDSB
                                   + (ks * 16 + (lane >> 4) * 8) * 2);
                    ldsm4(bh[np], bHi + ro);
                    ldsm4(bl[np], bLo + ro);
                }
#pragma unroll
                for (int mt = 0; mt < 2; mt++)
#pragma unroll
                    for (int j = 0; j < 4; j++) {
                        int np = j >> 1, sub = j & 1;
                        int nt = half * 4 + j;
                        mma16816(acc[mt][nt], ah[mt], bh[np][sub], bh[np][sub + 2]);
                        mma16816(acc[mt][nt], ah[mt], bl[np][sub], bl[np][sub + 2]);
                        mma16816(acc[mt][nt], al[mt], bh[np][sub], bh[np][sub + 2]);
                    }
            }
        }
    }

    __syncthreads();

    // ---- epilogue ----
#pragma unroll
    for (int mt = 0; mt < 2; mt++) {
        int rbase = m0 + wm * 32 + mt * 16 + (lane >> 2);
#pragma unroll
        for (int half = 0; half < 2; half++) {
            int r = rbase + half * 8;
            if (r >= M) continue;
            float dgv[Tt];
            if (msg) {
#pragma unroll
                for (int t = 0; t < Tt; t++) dgv[t] = (float)deg[t * Nn + r];
            }
#pragma unroll
            for (int nt = 0; nt < 8; nt++) {
                int col = n0 + wn * 64 + nt * 8 + (lane & 3) * 2;
                float v0 = acc[mt][nt][half * 2 + 0];
                float v1 = acc[mt][nt][half * 2 + 1];
                if (msg) {
#pragma unroll
                    for (int t = 0; t < Tt; t++) {
                        float2 b = *reinterpret_cast<const float2*>(bm + t * Hh + col);
                        v0 += dgv[t] * b.x;
                        v1 += dgv[t] * b.y;
                    }
                } else {
                    float2 b = *reinterpret_cast<const float2*>(bias + col);
                    v0 += b.x; v1 += b.y;
                }
                if (outHi) {
                    bf h0, l0, h1, l1;
                    split1(v0, h0, l0);
                    split1(v1, h1, l1);
                    size_t o = (size_t)r * Nout + col;
                    *reinterpret_cast<__nv_bfloat162*>(outHi + o) = __nv_bfloat162(h0, h1);
                    *reinterpret_cast<__nv_bfloat162*>(outLo + o) = __nv_bfloat162(l0, l1);
                } else {
                    *reinterpret_cast<float2*>(C + (size_t)r * Nout + col) = make_float2(v0, v1);
                }
            }
        }
    }
}

// ---------------- utility / conversion kernels ----------------
__global__ void copy_f4(const float4* __restrict__ s, float4* __restrict__ d, int n4) {
    int i = blockIdx.x * blockDim.x + threadIdx.x;
    int stride = gridDim.x * blockDim.x;
    for (; i < n4; i += stride) d[i] = s[i];
}
__global__ void cvt_split(const float* __restrict__ in, bf* __restrict__ hi,
                          bf* __restrict__ lo, int n4) {
    int i = blockIdx.x * blockDim.x + threadIdx.x;
    int stride = gridDim.x * blockDim.x;
    for (; i < n4; i += stride) {
        float4 v = reinterpret_cast<const float4*>(in)[i];
        bf h0,l0,h1,l1,h2,l2,h3,l3;
        split1(v.x, h0, l0); split1(v.y, h1, l1);
        split1(v.z, h2, l2); split1(v.w, h3, l3);
        *reinterpret_cast<__nv_bfloat162*>(hi + i*4)     = __nv_bfloat162(h0, h1);
        *reinterpret_cast<__nv_bfloat162*>(hi + i*4 + 2) = __nv_bfloat162(h2, h3);
        *reinterpret_cast<__nv_bfloat162*>(lo + i*4)     = __nv_bfloat162(l0, l1);
        *reinterpret_cast<__nv_bfloat162*>(lo + i*4 + 2) = __nv_bfloat162(l2, l3);
    }
}
__global__ void zero_i(int* p, int n) {
    int i = blockIdx.x * blockDim.x + threadIdx.x;
    if (i < n) p[i] = 0;
}
__global__ void count_deg(const int* __restrict__ edges, int* __restrict__ deg) {
    int idx = blockIdx.x * blockDim.x + threadIdx.x;
    if (idx < Tt * Ee) {
        int t = idx / Ee;
        int tgt = edges[idx * 2 + 1];
        atomicAdd(&deg[t * Nn + tgt], 1);
    }
}

// ---------------- CSR build ----------------
__global__ void scan1(const int* __restrict__ deg, int* __restrict__ off, int* __restrict__ bsum) {
    __shared__ int sm[1024];
    int t = threadIdx.x;
    int i = blockIdx.x * 1024 + t;
    int v = (i < TN) ? deg[i] : 0;
    sm[t] = v;
    __syncthreads();
    for (int d = 1; d < 1024; d <<= 1) {
        int x = (t >= d) ? sm[t - d] : 0;
        __syncthreads();
        sm[t] += x;
        __syncthreads();
    }
    if (i < TN) off[i + 1] = sm[t];
    if (t == 1023) bsum[blockIdx.x] = sm[t];
}
__global__ void scan2(const int* __restrict__ bsum, int* __restrict__ bofs, int nb) {
    __shared__ int sm[64];
    int t = threadIdx.x;
    int v = (t < nb) ? bsum[t] : 0;
    sm[t] = v;
    __syncthreads();
    for (int d = 1; d < 64; d <<= 1) {
        int x = (t >= d) ? sm[t - d] : 0;
        __syncthreads();
        sm[t] += x;
        __syncthreads();
    }
    bofs[t] = sm[t] - v;
}
__global__ void scan3(int* __restrict__ off, const int* __restrict__ bofs) {
    int i = blockIdx.x * blockDim.x + threadIdx.x;
    if (i == 0) off[0] = 0;
    if (i < TN) off[i + 1] += bofs[i >> 10];
}
__global__ void scatter_csr(const int* __restrict__ edges, const int* __restrict__ off,
                            int* __restrict__ cur, int* __restrict__ csr) {
    int idx = blockIdx.x * blockDim.x + threadIdx.x;
    if (idx >= Tt * Ee) return;
    int t = idx / Ee;
    int src = edges[idx * 2 + 0];
    int tgt = edges[idx * 2 + 1];
    int r = t * Nn + tgt;
    int p = off[r] + atomicAdd(&cur[r], 1);
    csr[p] = src;
}

// ---------------- CSR aggregation -> bf16 hi/lo S ----------------
__device__ __forceinline__ void st4_split(bf* hi, bf* lo, float4 a) {
    bf h0,l0,h1,l1,h2,l2,h3,l3;
    split1(a.x, h0, l0); split1(a.y, h1, l1);
    split1(a.z, h2, l2); split1(a.w, h3, l3);
    *reinterpret_cast<__nv_bfloat162*>(hi)     = __nv_bfloat162(h0, h1);
    *reinterpret_cast<__nv_bfloat162*>(hi + 2) = __nv_bfloat162(h2, h3);
    *reinterpret_cast<__nv_bfloat162*>(lo)     = __nv_bfloat162(l0, l1);
    *reinterpret_cast<__nv_bfloat162*>(lo + 2) = __nv_bfloat162(l2, l3);
}
__global__ void agg_csr(const float* __restrict__ h, const int* __restrict__ csr,
                        const int* __restrict__ off, bf* __restrict__ Shi,
                        bf* __restrict__ Slo) {
    int row = (blockIdx.x * blockDim.x + threadIdx.x) >> 5;
    int lane = threadIdx.x & 31;
    if (row >= TN) return;
    int s = off[row], e = off[row + 1];
    float4 a0 = make_float4(0.f,0.f,0.f,0.f), a1 = a0, a2 = a0, a3 = a0;
    for (int i = s; i < e; i++) {
        int src = __ldg(csr + i);
        const float4* hp = reinterpret_cast<const float4*>(h + (size_t)src * Hh);
        float4 v0 = hp[lane], v1 = hp[lane + 32], v2 = hp[lane + 64], v3 = hp[lane + 96];
        a0.x += v0.x; a0.y += v0.y; a0.z += v0.z; a0.w += v0.w;
        a1.x += v1.x; a1.y += v1.y; a1.z += v1.z; a1.w += v1.w;
        a2.x += v2.x; a2.y += v2.y; a2.z += v2.z; a2.w += v2.w;
        a3.x += v3.x; a3.y += v3.y; a3.z += v3.z; a3.w += v3.w;
    }
    bf* Hp = Shi + (size_t)row * Hh;
    bf* Lp = Slo + (size_t)row * Hh;
    st4_split(Hp + lane * 4,         Lp + lane * 4,         a0);
    st4_split(Hp + (lane + 32) * 4,  Lp + (lane + 32) * 4,  a1);
    st4_split(Hp + (lane + 64) * 4,  Lp + (lane + 64) * 4,  a2);
    st4_split(Hp + (lane + 96) * 4,  Lp + (lane + 96) * 4,  a3);
}

// ---------------- GRU elementwise (writes fp32 h + bf16 hi/lo h) ----------------
__global__ void gru_kernel(const float* __restrict__ gi, const float* __restrict__ gh,
                           const float* __restrict__ h, float* __restrict__ hout,
                           bf* __restrict__ hhi, bf* __restrict__ hlo) {
    int idx = blockIdx.x * blockDim.x + threadIdx.x;
    if (idx >= Nn * Hh) return;
    int n = idx / Hh;
    int j = idx - n * Hh;
    size_t base = (size_t)n * G3 + j;
    float ir = gi[base],          hr = gh[base];
    float iz = gi[base + Hh],     hz = gh[base + Hh];
    float in_ = gi[base + 2*Hh],  hn = gh[base + 2*Hh];
    float r = 1.f / (1.f + expf(-(ir + hr)));
    float z = 1.f / (1.f + expf(-(iz + hz)));
    float nv = tanhf(in_ + r * hn);
    float hv = (1.f - z) * nv + z * h[idx];
    hout[idx] = hv;
    bf hb, lb;
    split1(hv, hb, lb);
    hhi[idx] = hb;
    hlo[idx] = lb;
}

// ---------------- column max ----------------
__global__ void pmax_kernel(const float* __restrict__ X, float* __restrict__ pm) {
    int k = threadIdx.x;
    int b = blockIdx.x;
    float m = -INFINITY;
    int r0 = b * 100;
    for (int r = 0; r < 100; r++)
        m = fmaxf(m, X[(size_t)(r0 + r) * Hh + k]);
    pm[b * Hh + k] = m;
}
__global__ void fmax_kernel(const float* __restrict__ pm, float* __restrict__ out) {
    int k = threadIdx.x;
    float m = -INFINITY;
    for (int b = 0; b < 100; b++)
        m = fmaxf(m, pm[b * Hh + k]);
    out[k] = m;
}

// ---------------- launch ----------------
extern "C" void kernel_launch(void* const* d_in, const int* in_sizes, int n_in,
                              void* d_out, int out_size) {
    const float* x     = (const float*)d_in[0];
    const int*   edges = (const int*)  d_in[1];
    const float* W_msg = (const float*)d_in[2];
    const float* b_msg = (const float*)d_in[3];
    const float* W_ih  = (const float*)d_in[4];
    const float* W_hh  = (const float*)d_in[5];
    const float* b_ih  = (const float*)d_in[6];
    const float* b_hh  = (const float*)d_in[7];
    const float* fc_W  = (const float*)d_in[8];
    const float* fc_b  = (const float*)d_in[9];
    float* out = (float*)d_out;

    float *ph, *pgi, *pgh, *ppm;
    bf *pShi, *pSlo, *pihi, *pilo, *phhi, *phlo;
    bf *pWmh, *pWml, *pWih, *pWil, *pWhh, *pWhl, *pfch, *pfcl;
    int *pdeg, *poff, *pcur, *pcsr, *pbsum, *pbofs;
    cudaGetSymbolAddress((void**)&ph,    g_h);
    cudaGetSymbolAddress((void**)&pgi,   g_gi);
    cudaGetSymbolAddress((void**)&pgh,   g_gh);
    cudaGetSymbolAddress((void**)&ppm,   g_pm);
    cudaGetSymbolAddress((void**)&pShi,  g_Shi);
    cudaGetSymbolAddress((void**)&pSlo,  g_Slo);
    cudaGetSymbolAddress((void**)&pihi,  g_ihi);
    cudaGetSymbolAddress((void**)&pilo,  g_ilo);
    cudaGetSymbolAddress((void**)&phhi,  g_hhi);
    cudaGetSymbolAddress((void**)&phlo,  g_hlo);
    cudaGetSymbolAddress((void**)&pWmh,  g_Wmh);
    cudaGetSymbolAddress((void**)&pWml,  g_Wml);
    cudaGetSymbolAddress((void**)&pWih,  g_Wih);
    cudaGetSymbolAddress((void**)&pWil,  g_Wil);
    cudaGetSymbolAddress((void**)&pWhh,  g_Whh);
    cudaGetSymbolAddress((void**)&pWhl,  g_Whl);
    cudaGetSymbolAddress((void**)&pfch,  g_fch);
    cudaGetSymbolAddress((void**)&pfcl,  g_fcl);
    cudaGetSymbolAddress((void**)&pdeg,  g_deg);
    cudaGetSymbolAddress((void**)&poff,  g_off);
    cudaGetSymbolAddress((void**)&pcur,  g_cur);
    cudaGetSymbolAddress((void**)&pcsr,  g_csr);
    cudaGetSymbolAddress((void**)&pbsum, g_bsum);
    cudaGetSymbolAddress((void**)&pbofs, g_bofs);

    cudaFuncSetAttribute(mma_gemm, cudaFuncAttributeMaxDynamicSharedMemorySize, SMEM_BYTES);

    float* hc = ph;
    float* hn = ph + (size_t)Nn * Hh;

    // init: h=x (fp32 + bf16 split), weight splits, CSR
    copy_f4<<<2048, 256>>>((const float4*)x, (float4*)hc, Nn * Hh / 4);
    cvt_split<<<2048, 256>>>(x, phhi, phlo, Nn * Hh / 4);
    cvt_split<<<2048, 256>>>(W_msg, pWmh, pWml, WMSG_SZ / 4);
    cvt_split<<<2048, 256>>>(W_ih,  pWih, pWil, WIH_SZ / 4);
    cvt_split<<<2048, 256>>>(W_hh,  pWhh, pWhl, WIH_SZ / 4);
    cvt_split<<<1024, 256>>>(fc_W,  pfch, pfcl, FC_SZ / 4);

    zero_i<<<(TN + 255) / 256, 256>>>(pdeg, TN);
    zero_i<<<(TN + 255) / 256, 256>>>(pcur, TN);
    count_deg<<<(Tt * Ee + 255) / 256, 256>>>(edges, pdeg);
    scan1<<<(TN + 1023) / 1024, 1024>>>(pdeg, poff, pbsum);
    scan2<<<1, 64>>>(pbsum, pbofs, (TN + 1023) / 1024);
    scan3<<<(TN + 255) / 256, 256>>>(poff, pbofs);
    scatter_csr<<<(Tt * Ee + 255) / 256, 256>>>(edges, poff, pcur, pcsr);

    dim3 gm((Nn + 127) / 128, Hh / 128);    // 79 x 4
    dim3 gg((Nn + 127) / 128, G3 / 128);    // 79 x 12
    int aggBlocks = (TN * 32 + 255) / 256;

    for (int layer = 0; layer < Ll; layer++) {
        const bf* Wmh_l = pWmh + (size_t)layer * Tt * Hh * Hh;
        const bf* Wml_l = pWml + (size_t)layer * Tt * Hh * Hh;
        const bf* Wih_l = pWih + (size_t)layer * G3 * Hh;
        const bf* Wil_l = pWil + (size_t)layer * G3 * Hh;
        const bf* Whh_l = pWhh + (size_t)layer * G3 * Hh;
        const bf* Whl_l = pWhl + (size_t)layer * G3 * Hh;
        const float* bm_l  = b_msg + (size_t)layer * Tt * Hh;
        const float* bih_l = b_ih  + (size_t)layer * G3;
        const float* bhh_l = b_hh  + (size_t)layer * G3;
        for (int s = 0; s < 2; s++) {
            agg_csr<<<aggBlocks, 256>>>(hc, pcsr, poff, pShi, pSlo);
            mma_gemm<<<gm, 256, SMEM_BYTES>>>(pShi, pSlo, Wmh_l, Wml_l,
                                              nullptr, bm_l, pdeg,
                                              nullptr, pihi, pilo, Nn, Hh, Tt);
            mma_gemm<<<gg, 256, SMEM_BYTES>>>(pihi, pilo, Wih_l, Wil_l,
                                              bih_l, nullptr, nullptr,
                                              pgi, nullptr, nullptr, Nn, G3, 1);
            mma_gemm<<<gg, 256, SMEM_BYTES>>>(phhi, phlo, Whh_l, Whl_l,
                                              bhh_l, nullptr, nullptr,
                                              pgh, nullptr, nullptr, Nn, G3, 1);
            gru_kernel<<<(Nn * Hh + 255) / 256, 256>>>(pgi, pgh, hc, hn, phhi, phlo);
            float* t = hc; hc = hn; hn = t;
        }
    }

    mma_gemm<<<gm, 256, SMEM_BYTES>>>(phhi, phlo, pfch, pfcl,
                                      fc_b, nullptr, nullptr,
                                      pgi, nullptr, nullptr, Nn, Hh, 1);
    pmax_kernel<<<100, 512>>>(pgi, ppm);
    fmax_kernel<<<1, 512>>>(ppm, out);
}

// round 8
// speedup vs baseline: 1.2309x; 1.0777x over previous
#include <cuda_runtime.h>
#include <cuda_bf16.h>
#include <math.h>

#define Nn 10000
#define Hh 512
#define Tt 4
#define Ee 40000
#define Ll 2
#define G3 (3*Hh)
#define TN (Tt*Nn)
#define WMSG_SZ (Ll*Tt*Hh*Hh)
#define WIH_SZ  (Ll*G3*Hh)
#define FC_SZ   (Hh*Hh)

typedef unsigned long long u64;
typedef unsigned int u32;
typedef __nv_bfloat16 bf;

// ---------------- device scratch ----------------
__device__ __align__(16) float g_h  [2*(size_t)Nn*Hh];
__device__ __align__(16) float g_gi [(size_t)Nn*G3];
__device__ __align__(16) float g_gh [(size_t)Nn*G3];
__device__ __align__(16) float g_pm [100*Hh];
__device__ __align__(16) bf g_Shi[(size_t)TN*Hh];
__device__ __align__(16) bf g_Slo[(size_t)TN*Hh];
__device__ __align__(16) bf g_ihi[(size_t)Nn*Hh];
__device__ __align__(16) bf g_ilo[(size_t)Nn*Hh];
__device__ __align__(16) bf g_hhi[(size_t)Nn*Hh];
__device__ __align__(16) bf g_hlo[(size_t)Nn*Hh];
__device__ __align__(16) bf g_Wmh[WMSG_SZ];
__device__ __align__(16) bf g_Wml[WMSG_SZ];
__device__ __align__(16) bf g_Wih[WIH_SZ];
__device__ __align__(16) bf g_Wil[WIH_SZ];
__device__ __align__(16) bf g_Whh[WIH_SZ];
__device__ __align__(16) bf g_Whl[WIH_SZ];
__device__ __align__(16) bf g_fch[FC_SZ];
__device__ __align__(16) bf g_fcl[FC_SZ];
__device__ int g_deg [TN];
__device__ int g_off [TN + 1];
__device__ int g_cur [TN];
__device__ int g_csr [Tt*Ee];
__device__ int g_bsum[64];
__device__ int g_bofs[64];

// ---------------- smem geometry: interleaved hi/lo, 128B swizzled rows ----------------
// A tile: 128 rows x 128B (hi chunks 0-3, lo chunks 4-7), swizzle: pchunk = lc ^ (row&7)
#define TILE_SZ 16384               // 128 * 128
#define BUFSZ   (2*TILE_SZ)         // A tile + B tile
#define NSTAGE  3
#define SMEM_BYTES (NSTAGE*BUFSZ)   // 98304

__device__ __forceinline__ u32 smem_u32(const void* p) {
    u32 a;
    asm("{ .reg .u64 t; cvta.to.shared.u64 t, %1; cvt.u32.u64 %0, t; }" : "=r"(a) : "l"(p));
    return a;
}
__device__ __forceinline__ void ldsm4(u32 r[4], u32 addr) {
    asm volatile("ldmatrix.sync.aligned.m8n8.x4.shared.b16 {%0,%1,%2,%3}, [%4];"
                 : "=r"(r[0]), "=r"(r[1]), "=r"(r[2]), "=r"(r[3]) : "r"(addr));
}
__device__ __forceinline__ void mma16816(float d[4], const u32 a[4], u32 b0, u32 b1) {
    asm volatile("mma.sync.aligned.m16n8k16.row.col.f32.bf16.bf16.f32 "
                 "{%0,%1,%2,%3}, {%4,%5,%6,%7}, {%8,%9}, {%0,%1,%2,%3};"
                 : "+f"(d[0]), "+f"(d[1]), "+f"(d[2]), "+f"(d[3])
                 : "r"(a[0]), "r"(a[1]), "r"(a[2]), "r"(a[3]), "r"(b0), "r"(b1));
}
__device__ __forceinline__ void split1(float v, bf& h, bf& l) {
    h = __float2bfloat16(v);
    l = __float2bfloat16(v - __bfloat162float(h));
}
__device__ __forceinline__ void cpa16(u32 saddr, const void* g) {
    asm volatile("cp.async.cg.shared.global [%0], [%1], 16;" :: "r"(saddr), "l"(g) : "memory");
}
#define CPA_COMMIT() asm volatile("cp.async.commit_group;" ::: "memory")
#define CPA_WAIT0()  asm volatile("cp.async.wait_group 0;" ::: "memory")
#define CPA_WAIT1()  asm volatile("cp.async.wait_group 1;" ::: "memory")

// swizzled byte offset inside a tile
__device__ __forceinline__ u32 tswz(int row, int lc) {
    return (u32)(row * 128 + ((lc ^ (row & 7)) << 4));
}

// ---- cp.async loader: combined hi/lo tile, 128 rows x 32 bf16 per half ----
// 1024 16B-chunks, 256 threads -> 4 chunks each
__device__ __forceinline__ void cpa_tile2(const bf* __restrict__ hi, const bf* __restrict__ lo,
                                          int rowMax, int r0, int tid, u32 sdst) {
#pragma unroll
    for (int i = 0; i < 4; i++) {
        int c = i * 256 + tid;
        int row = c >> 3;
        int lc  = c & 7;
        int m = r0 + row;
        if (m >= rowMax) m = rowMax - 1;   // clamp: ghost rows never written out
        const bf* src = (lc < 4) ? hi + (size_t)m * Hh + lc * 8
                                 : lo + (size_t)m * Hh + (lc - 4) * 8;
        cpa16(sdst + tswz(row, lc), src);
    }
}

// ============ bf16 3-split HMMA GEMM, 3-stage cp.async pipeline (2 CTAs/SM) ============
__global__ __launch_bounds__(256, 2)
void mma_gemm(const bf* __restrict__ Ahi, const bf* __restrict__ Alo,
              const bf* __restrict__ Bhi, const bf* __restrict__ Blo,
              const float* __restrict__ bias, const float* __restrict__ bm,
              const int* __restrict__ deg,
              float* __restrict__ C, bf* __restrict__ outHi, bf* __restrict__ outLo,
              int M, int Nout, int nSeg)
{
    extern __shared__ __align__(16) char smem[];
    const int tid = threadIdx.x;
    const int lane = tid & 31, wid = tid >> 5;
    const int wm = wid & 3, wn = wid >> 2;
    const int m0 = blockIdx.x * 128, n0 = blockIdx.y * 128;
    const int NKB = nSeg * 16;
    const bool msg = (nSeg > 1);
    u32 sb = smem_u32(smem);

    float acc[2][8][4];
#pragma unroll
    for (int i = 0; i < 2; i++)
#pragma unroll
        for (int j = 0; j < 8; j++)
#pragma unroll
            for (int k = 0; k < 4; k++) acc[i][j][k] = 0.f;

    // prologue: stages 0 and 1
#pragma unroll
    for (int s = 0; s < 2; s++) {
        int tseg = s >> 4, koff = (s & 15) * 32;
        size_t ao = (size_t)tseg * ((size_t)Nn * Hh) + koff;
        size_t bo = (size_t)tseg * ((size_t)Hh * Hh) + koff;
        u32 dst = sb + s * BUFSZ;
        cpa_tile2(Ahi + ao, Alo + ao, M, m0, tid, dst);
        cpa_tile2(Bhi + bo, Blo + bo, 1 << 30, n0, tid, dst + TILE_SZ);
        CPA_COMMIT();
    }

    int buf = 0;
    for (int kb = 0; kb < NKB; kb++) {
        if (kb == NKB - 1) { CPA_WAIT0(); } else { CPA_WAIT1(); }
        __syncthreads();          // buf[kb] ready; all warps done reading buf[kb] slot's previous tenant

        if (kb + 2 < NKB) {       // prefetch kb+2; has ~2 k-blocks of MMA to land
            int kn = kb + 2;
            int tseg = kn >> 4, koff = (kn & 15) * 32;
            size_t ao = (size_t)tseg * ((size_t)Nn * Hh) + koff;
            size_t bo = (size_t)tseg * ((size_t)Hh * Hh) + koff;
            int bn = buf + 2; if (bn >= NSTAGE) bn -= NSTAGE;
            u32 dst = sb + bn * BUFSZ;
            cpa_tile2(Ahi + ao, Alo + ao, M, m0, tid, dst);
            cpa_tile2(Bhi + bo, Blo + bo, 1 << 30, n0, tid, dst + TILE_SZ);
            CPA_COMMIT();
        }

        u32 aT = sb + buf * BUFSZ;
        u32 bT = aT + TILE_SZ;
#pragma unroll
        for (int ks = 0; ks < 2; ks++) {
            int lcA = 2 * ks + (lane >> 4);
            u32 ah[2][4], al[2][4];
#pragma unroll
            for (int mt = 0; mt < 2; mt++) {
                int row = wm * 32 + mt * 16 + (lane & 15);
                ldsm4(ah[mt], aT + tswz(row, lcA));
                ldsm4(al[mt], aT + tswz(row, lcA + 4));
            }
#pragma unroll
            for (int half = 0; half < 2; half++) {
                u32 bh[2][4], bl[2][4];
#pragma unroll
                for (int np = 0; np < 2; np++) {
                    int np2 = half * 2 + np;
                    int row = wn * 64 + np2 * 16 + (lane & 7) + ((lane >> 3) & 1) * 8;
                    ldsm4(bh[np], bT + tswz(row, lcA));
                    ldsm4(bl[np], bT + tswz(row, lcA + 4));
                }
#pragma unroll
                for (int mt = 0; mt < 2; mt++)
#pragma unroll
                    for (int j = 0; j < 4; j++) {
                        int np = j >> 1, sub = j & 1;
                        int nt = half * 4 + j;
                        mma16816(acc[mt][nt], ah[mt], bh[np][sub], bh[np][sub + 2]);
                        mma16816(acc[mt][nt], ah[mt], bl[np][sub], bl[np][sub + 2]);
                        mma16816(acc[mt][nt], al[mt], bh[np][sub], bh[np][sub + 2]);
                    }
            }
        }
        buf++; if (buf >= NSTAGE) buf = 0;
    }

    __syncthreads();

    // ---- epilogue ----
#pragma unroll
    for (int mt = 0; mt < 2; mt++) {
        int rbase = m0 + wm * 32 + mt * 16 + (lane >> 2);
#pragma unroll
        for (int half = 0; half < 2; half++) {
            int r = rbase + half * 8;
            if (r >= M) continue;
            float dgv[Tt];
            if (msg) {
#pragma unroll
                for (int t = 0; t < Tt; t++) dgv[t] = (float)deg[t * Nn + r];
            }
#pragma unroll
            for (int nt = 0; nt < 8; nt++) {
                int col = n0 + wn * 64 + nt * 8 + (lane & 3) * 2;
                float v0 = acc[mt][nt][half * 2 + 0];
                float v1 = acc[mt][nt][half * 2 + 1];
                if (msg) {
#pragma unroll
                    for (int t = 0; t < Tt; t++) {
                        float2 b = *reinterpret_cast<const float2*>(bm + t * Hh + col);
                        v0 += dgv[t] * b.x;
                        v1 += dgv[t] * b.y;
                    }
                } else {
                    float2 b = *reinterpret_cast<const float2*>(bias + col);
                    v0 += b.x; v1 += b.y;
                }
                if (outHi) {
                    bf h0, l0, h1, l1;
                    split1(v0, h0, l0);
                    split1(v1, h1, l1);
                    size_t o = (size_t)r * Nout + col;
                    *reinterpret_cast<__nv_bfloat162*>(outHi + o) = __nv_bfloat162(h0, h1);
                    *reinterpret_cast<__nv_bfloat162*>(outLo + o) = __nv_bfloat162(l0, l1);
                } else {
                    *reinterpret_cast<float2*>(C + (size_t)r * Nout + col) = make_float2(v0, v1);
                }
            }
        }
    }
}

// ---------------- utility / conversion kernels ----------------
__global__ void copy_f4(const float4* __restrict__ s, float4* __restrict__ d, int n4) {
    int i = blockIdx.x * blockDim.x + threadIdx.x;
    int stride = gridDim.x * blockDim.x;
    for (; i < n4; i += stride) d[i] = s[i];
}
__global__ void cvt_split(const float* __restrict__ in, bf* __restrict__ hi,
                          bf* __restrict__ lo, int n4) {
    int i = blockIdx.x * blockDim.x + threadIdx.x;
    int stride = gridDim.x * blockDim.x;
    for (; i < n4; i += stride) {
        float4 v = reinterpret_cast<const float4*>(in)[i];
        bf h0,l0,h1,l1,h2,l2,h3,l3;
        split1(v.x, h0, l0); split1(v.y, h1, l1);
        split1(v.z, h2, l2); split1(v.w, h3, l3);
        *reinterpret_cast<__nv_bfloat162*>(hi + i*4)     = __nv_bfloat162(h0, h1);
        *reinterpret_cast<__nv_bfloat162*>(hi + i*4 + 2) = __nv_bfloat162(h2, h3);
        *reinterpret_cast<__nv_bfloat162*>(lo + i*4)     = __nv_bfloat162(l0, l1);
        *reinterpret_cast<__nv_bfloat162*>(lo + i*4 + 2) = __nv_bfloat162(l2, l3);
    }
}
__global__ void zero_i(int* p, int n) {
    int i = blockIdx.x * blockDim.x + threadIdx.x;
    if (i < n) p[i] = 0;
}
__global__ void count_deg(const int* __restrict__ edges, int* __restrict__ deg) {
    int idx = blockIdx.x * blockDim.x + threadIdx.x;
    if (idx < Tt * Ee) {
        int t = idx / Ee;
        int tgt = edges[idx * 2 + 1];
        atomicAdd(&deg[t * Nn + tgt], 1);
    }
}

// ---------------- CSR build ----------------
__global__ void scan1(const int* __restrict__ deg, int* __restrict__ off, int* __restrict__ bsum) {
    __shared__ int sm[1024];
    int t = threadIdx.x;
    int i = blockIdx.x * 1024 + t;
    int v = (i < TN) ? deg[i] : 0;
    sm[t] = v;
    __syncthreads();
    for (int d = 1; d < 1024; d <<= 1) {
        int x = (t >= d) ? sm[t - d] : 0;
        __syncthreads();
        sm[t] += x;
        __syncthreads();
    }
    if (i < TN) off[i + 1] = sm[t];
    if (t == 1023) bsum[blockIdx.x] = sm[t];
}
__global__ void scan2(const int* __restrict__ bsum, int* __restrict__ bofs, int nb) {
    __shared__ int sm[64];
    int t = threadIdx.x;
    int v = (t < nb) ? bsum[t] : 0;
    sm[t] = v;
    __syncthreads();
    for (int d = 1; d < 64; d <<= 1) {
        int x = (t >= d) ? sm[t - d] : 0;
        __syncthreads();
        sm[t] += x;
        __syncthreads();
    }
    bofs[t] = sm[t] - v;
}
__global__ void scan3(int* __restrict__ off, const int* __restrict__ bofs) {
    int i = blockIdx.x * blockDim.x + threadIdx.x;
    if (i == 0) off[0] = 0;
    if (i < TN) off[i + 1] += bofs[i >> 10];
}
__global__ void scatter_csr(const int* __restrict__ edges, const int* __restrict__ off,
                            int* __restrict__ cur, int* __restrict__ csr) {
    int idx = blockIdx.x * blockDim.x + threadIdx.x;
    if (idx >= Tt * Ee) return;
    int t = idx / Ee;
    int src = edges[idx * 2 + 0];
    int tgt = edges[idx * 2 + 1];
    int r = t * Nn + tgt;
    int p = off[r] + atomicAdd(&cur[r], 1);
    csr[p] = src;
}

// ---------------- CSR aggregation -> bf16 hi/lo S ----------------
__device__ __forceinline__ void st4_split(bf* hi, bf* lo, float4 a) {
    bf h0,l0,h1,l1,h2,l2,h3,l3;
    split1(a.x, h0, l0); split1(a.y, h1, l1);
    split1(a.z, h2, l2); split1(a.w, h3, l3);
    *reinterpret_cast<__nv_bfloat162*>(hi)     = __nv_bfloat162(h0, h1);
    *reinterpret_cast<__nv_bfloat162*>(hi + 2) = __nv_bfloat162(h2, h3);
    *reinterpret_cast<__nv_bfloat162*>(lo)     = __nv_bfloat162(l0, l1);
    *reinterpret_cast<__nv_bfloat162*>(lo + 2) = __nv_bfloat162(l2, l3);
}
__global__ void agg_csr(const float* __restrict__ h, const int* __restrict__ csr,
                        const int* __restrict__ off, bf* __restrict__ Shi,
                        bf* __restrict__ Slo) {
    int row = (blockIdx.x * blockDim.x + threadIdx.x) >> 5;
    int lane = threadIdx.x & 31;
    if (row >= TN) return;
    int s = off[row], e = off[row + 1];
    float4 a0 = make_float4(0.f,0.f,0.f,0.f), a1 = a0, a2 = a0, a3 = a0;
    for (int i = s; i < e; i++) {
        int src = __ldg(csr + i);
        const float4* hp = reinterpret_cast<const float4*>(h + (size_t)src * Hh);
        float4 v0 = hp[lane], v1 = hp[lane + 32], v2 = hp[lane + 64], v3 = hp[lane + 96];
        a0.x += v0.x; a0.y += v0.y; a0.z += v0.z; a0.w += v0.w;
        a1.x += v1.x; a1.y += v1.y; a1.z += v1.z; a1.w += v1.w;
        a2.x += v2.x; a2.y += v2.y; a2.z += v2.z; a2.w += v2.w;
        a3.x += v3.x; a3.y += v3.y; a3.z += v3.z; a3.w += v3.w;
    }
    bf* Hp = Shi + (size_t)row * Hh;
    bf* Lp = Slo + (size_t)row * Hh;
    st4_split(Hp + lane * 4,         Lp + lane * 4,         a0);
    st4_split(Hp + (lane + 32) * 4,  Lp + (lane + 32) * 4,  a1);
    st4_split(Hp + (lane + 64) * 4,  Lp + (lane + 64) * 4,  a2);
    st4_split(Hp + (lane + 96) * 4,  Lp + (lane + 96) * 4,  a3);
}

// ---------------- GRU elementwise ----------------
__global__ void gru_kernel(const float* __restrict__ gi, const float* __restrict__ gh,
                           const float* __restrict__ h, float* __restrict__ hout,
                           bf* __restrict__ hhi, bf* __restrict__ hlo) {
    int idx = blockIdx.x * blockDim.x + threadIdx.x;
    if (idx >= Nn * Hh) return;
    int n = idx / Hh;
    int j = idx - n * Hh;
    size_t base = (size_t)n * G3 + j;
    float ir = gi[base],          hr = gh[base];
    float iz = gi[base + Hh],     hz = gh[base + Hh];
    float in_ = gi[base + 2*Hh],  hn = gh[base + 2*Hh];
    float r = 1.f / (1.f + expf(-(ir + hr)));
    float z = 1.f / (1.f + expf(-(iz + hz)));
    float nv = tanhf(in_ + r * hn);
    float hv = (1.f - z) * nv + z * h[idx];
    hout[idx] = hv;
    bf hb, lb;
    split1(hv, hb, lb);
    hhi[idx] = hb;
    hlo[idx] = lb;
}

// ---------------- column max ----------------
__global__ void pmax_kernel(const float* __restrict__ X, float* __restrict__ pm) {
    int k = threadIdx.x;
    int b = blockIdx.x;
    float m = -INFINITY;
    int r0 = b * 100;
    for (int r = 0; r < 100; r++)
        m = fmaxf(m, X[(size_t)(r0 + r) * Hh + k]);
    pm[b * Hh + k] = m;
}
__global__ void fmax_kernel(const float* __restrict__ pm, float* __restrict__ out) {
    int k = threadIdx.x;
    float m = -INFINITY;
    for (int b = 0; b < 100; b++)
        m = fmaxf(m, pm[b * Hh + k]);
    out[k] = m;
}

// ---------------- launch ----------------
extern "C" void kernel_launch(void* const* d_in, const int* in_sizes, int n_in,
                              void* d_out, int out_size) {
    const float* x     = (const float*)d_in[0];
    const int*   edges = (const int*)  d_in[1];
    const float* W_msg = (const float*)d_in[2];
    const float* b_msg = (const float*)d_in[3];
    const float* W_ih  = (const float*)d_in[4];
    const float* W_hh  = (const float*)d_in[5];
    const float* b_ih  = (const float*)d_in[6];
    const float* b_hh  = (const float*)d_in[7];
    const float* fc_W  = (const float*)d_in[8];
    const float* fc_b  = (const float*)d_in[9];
    float* out = (float*)d_out;

    float *ph, *pgi, *pgh, *ppm;
    bf *pShi, *pSlo, *pihi, *pilo, *phhi, *phlo;
    bf *pWmh, *pWml, *pWih, *pWil, *pWhh, *pWhl, *pfch, *pfcl;
    int *pdeg, *poff, *pcur, *pcsr, *pbsum, *pbofs;
    cudaGetSymbolAddress((void**)&ph,    g_h);
    cudaGetSymbolAddress((void**)&pgi,   g_gi);
    cudaGetSymbolAddress((void**)&pgh,   g_gh);
    cudaGetSymbolAddress((void**)&ppm,   g_pm);
    cudaGetSymbolAddress((void**)&pShi,  g_Shi);
    cudaGetSymbolAddress((void**)&pSlo,  g_Slo);
    cudaGetSymbolAddress((void**)&pihi,  g_ihi);
    cudaGetSymbolAddress((void**)&pilo,  g_ilo);
    cudaGetSymbolAddress((void**)&phhi,  g_hhi);
    cudaGetSymbolAddress((void**)&phlo,  g_hlo);
    cudaGetSymbolAddress((void**)&pWmh,  g_Wmh);
    cudaGetSymbolAddress((void**)&pWml,  g_Wml);
    cudaGetSymbolAddress((void**)&pWih,  g_Wih);
    cudaGetSymbolAddress((void**)&pWil,  g_Wil);
    cudaGetSymbolAddress((void**)&pWhh,  g_Whh);
    cudaGetSymbolAddress((void**)&pWhl,  g_Whl);
    cudaGetSymbolAddress((void**)&pfch,  g_fch);
    cudaGetSymbolAddress((void**)&pfcl,  g_fcl);
    cudaGetSymbolAddress((void**)&pdeg,  g_deg);
    cudaGetSymbolAddress((void**)&poff,  g_off);
    cudaGetSymbolAddress((void**)&pcur,  g_cur);
    cudaGetSymbolAddress((void**)&pcsr,  g_csr);
    cudaGetSymbolAddress((void**)&pbsum, g_bsum);
    cudaGetSymbolAddress((void**)&pbofs, g_bofs);

    cudaFuncSetAttribute(mma_gemm, cudaFuncAttributeMaxDynamicSharedMemorySize, SMEM_BYTES);

    float* hc = ph;
    float* hn = ph + (size_t)Nn * Hh;

    copy_f4<<<2048, 256>>>((const float4*)x, (float4*)hc, Nn * Hh / 4);
    cvt_split<<<2048, 256>>>(x, phhi, phlo, Nn * Hh / 4);
    cvt_split<<<2048, 256>>>(W_msg, pWmh, pWml, WMSG_SZ / 4);
    cvt_split<<<2048, 256>>>(W_ih,  pWih, pWil, WIH_SZ / 4);
    cvt_split<<<2048, 256>>>(W_hh,  pWhh, pWhl, WIH_SZ / 4);
    cvt_split<<<1024, 256>>>(fc_W,  pfch, pfcl, FC_SZ / 4);

    zero_i<<<(TN + 255) / 256, 256>>>(pdeg, TN);
    zero_i<<<(TN + 255) / 256, 256>>>(pcur, TN);
    count_deg<<<(Tt * Ee + 255) / 256, 256>>>(edges, pdeg);
    scan1<<<(TN + 1023) / 1024, 1024>>>(pdeg, poff, pbsum);
    scan2<<<1, 64>>>(pbsum, pbofs, (TN + 1023) / 1024);
    scan3<<<(TN + 255) / 256, 256>>>(poff, pbofs);
    scatter_csr<<<(Tt * Ee + 255) / 256, 256>>>(edges, poff, pcur, pcsr);

    dim3 gm((Nn + 127) / 128, Hh / 128);    // 79 x 4
    dim3 gg((Nn + 127) / 128, G3 / 128);    // 79 x 12
    int aggBlocks = (TN * 32 + 255) / 256;

    for (int layer = 0; layer < Ll; layer++) {
        const bf* Wmh_l = pWmh + (size_t)layer * Tt * Hh * Hh;
        const bf* Wml_l = pWml + (size_t)layer * Tt * Hh * Hh;
        const bf* Wih_l = pWih + (size_t)layer * G3 * Hh;
        const bf* Wil_l = pWil + (size_t)layer * G3 * Hh;
        const bf* Whh_l = pWhh + (size_t)layer * G3 * Hh;
        const bf* Whl_l = pWhl + (size_t)layer * G3 * Hh;
        const float* bm_l  = b_msg + (size_t)layer * Tt * Hh;
        const float* bih_l = b_ih  + (size_t)layer * G3;
        const float* bhh_l = b_hh  + (size_t)layer * G3;
        for (int s = 0; s < 2; s++) {
            agg_csr<<<aggBlocks, 256>>>(hc, pcsr, poff, pShi, pSlo);
            mma_gemm<<<gm, 256, SMEM_BYTES>>>(pShi, pSlo, Wmh_l, Wml_l,
                                              nullptr, bm_l, pdeg,
                                              nullptr, pihi, pilo, Nn, Hh, Tt);
            mma_gemm<<<gg, 256, SMEM_BYTES>>>(pihi, pilo, Wih_l, Wil_l,
                                              bih_l, nullptr, nullptr,
                                              pgi, nullptr, nullptr, Nn, G3, 1);
            mma_gemm<<<gg, 256, SMEM_BYTES>>>(phhi, phlo, Whh_l, Whl_l,
                                              bhh_l, nullptr, nullptr,
                                              pgh, nullptr, nullptr, Nn, G3, 1);
            gru_kernel<<<(Nn * Hh + 255) / 256, 256>>>(pgi, pgh, hc, hn, phhi, phlo);
            float* t = hc; hc = hn; hn = t;
        }
    }

    mma_gemm<<<gm, 256, SMEM_BYTES>>>(phhi, phlo, pfch, pfcl,
                                      fc_b, nullptr, nullptr,
                                      pgi, nullptr, nullptr, Nn, Hh, 1);
    pmax_kernel<<<100, 512>>>(pgi, ppm);
    fmax_kernel<<<1, 512>>>(ppm, out);
}

// round 9
// speedup vs baseline: 1.3965x; 1.1346x over previous
#include <cuda_runtime.h>
#include <cuda_bf16.h>
#include <math.h>

#define Nn 10000
#define Hh 512
#define Tt 4
#define Ee 40000
#define Ll 2
#define G3 (3*Hh)
#define TN (Tt*Nn)
#define WMSG_SZ (Ll*Tt*Hh*Hh)
#define WIH_SZ  (Ll*G3*Hh)
#define FC_SZ   (Hh*Hh)

typedef unsigned long long u64;
typedef unsigned int u32;
typedef __nv_bfloat16 bf;

// ---------------- device scratch ----------------
__device__ __align__(16) float g_h  [2*(size_t)Nn*Hh];
__device__ __align__(16) float g_gi [(size_t)Nn*G3];
__device__ __align__(16) float g_gh [(size_t)Nn*G3];
__device__ __align__(16) float g_pm [100*Hh];
__device__ __align__(16) bf g_Shi[(size_t)TN*Hh];
__device__ __align__(16) bf g_Slo[(size_t)TN*Hh];
__device__ __align__(16) bf g_ihi[(size_t)Nn*Hh];
__device__ __align__(16) bf g_ilo[(size_t)Nn*Hh];
__device__ __align__(16) bf g_hhi[(size_t)Nn*Hh];
__device__ __align__(16) bf g_hlo[(size_t)Nn*Hh];
__device__ __align__(16) bf g_Wmh[WMSG_SZ];
__device__ __align__(16) bf g_Wml[WMSG_SZ];
__device__ __align__(16) bf g_Wih[WIH_SZ];
__device__ __align__(16) bf g_Wil[WIH_SZ];
__device__ __align__(16) bf g_Whh[WIH_SZ];
__device__ __align__(16) bf g_Whl[WIH_SZ];
__device__ __align__(16) bf g_fch[FC_SZ];
__device__ __align__(16) bf g_fcl[FC_SZ];
__device__ int g_deg [TN];
__device__ int g_off [TN + 1];
__device__ int g_cur [TN];
__device__ int g_csr [Tt*Ee];
__device__ int g_bsum[64];
__device__ int g_bofs[64];

// ---------------- smem geometry: interleaved hi/lo, 128B swizzled rows ----------------
#define TILE_SZ 16384
#define BUFSZ   (2*TILE_SZ)
#define NSTAGE  3
#define SMEM_BYTES (NSTAGE*BUFSZ)   // 98304

__device__ __forceinline__ u32 smem_u32(const void* p) {
    u32 a;
    asm("{ .reg .u64 t; cvta.to.shared.u64 t, %1; cvt.u32.u64 %0, t; }" : "=r"(a) : "l"(p));
    return a;
}
__device__ __forceinline__ void ldsm4(u32 r[4], u32 addr) {
    asm volatile("ldmatrix.sync.aligned.m8n8.x4.shared.b16 {%0,%1,%2,%3}, [%4];"
                 : "=r"(r[0]), "=r"(r[1]), "=r"(r[2]), "=r"(r[3]) : "r"(addr));
}
__device__ __forceinline__ void mma16816(float d[4], const u32 a[4], u32 b0, u32 b1) {
    asm volatile("mma.sync.aligned.m16n8k16.row.col.f32.bf16.bf16.f32 "
                 "{%0,%1,%2,%3}, {%4,%5,%6,%7}, {%8,%9}, {%0,%1,%2,%3};"
                 : "+f"(d[0]), "+f"(d[1]), "+f"(d[2]), "+f"(d[3])
                 : "r"(a[0]), "r"(a[1]), "r"(a[2]), "r"(a[3]), "r"(b0), "r"(b1));
}
__device__ __forceinline__ void split1(float v, bf& h, bf& l) {
    h = __float2bfloat16(v);
    l = __float2bfloat16(v - __bfloat162float(h));
}
__device__ __forceinline__ void cpa16(u32 saddr, const void* g) {
    asm volatile("cp.async.cg.shared.global [%0], [%1], 16;" :: "r"(saddr), "l"(g) : "memory");
}
#define CPA_COMMIT() asm volatile("cp.async.commit_group;" ::: "memory")
#define CPA_WAIT0()  asm volatile("cp.async.wait_group 0;" ::: "memory")
#define CPA_WAIT1()  asm volatile("cp.async.wait_group 1;" ::: "memory")

__device__ __forceinline__ u32 tswz(int row, int lc) {
    return (u32)(row * 128 + ((lc ^ (row & 7)) << 4));
}

__device__ __forceinline__ void cpa_tile2(const bf* __restrict__ hi, const bf* __restrict__ lo,
                                          int rowMax, int r0, int tid, u32 sdst) {
#pragma unroll
    for (int i = 0; i < 4; i++) {
        int c = i * 256 + tid;
        int row = c >> 3;
        int lc  = c & 7;
        int m = r0 + row;
        if (m >= rowMax) m = rowMax - 1;
        const bf* src = (lc < 4) ? hi + (size_t)m * Hh + lc * 8
                                 : lo + (size_t)m * Hh + (lc - 4) * 8;
        cpa16(sdst + tswz(row, lc), src);
    }
}

// ============ shared GEMM body: bf16 3-split HMMA, 3-stage cp.async ============
__device__ __forceinline__ void gemm_body(
    const bf* __restrict__ Ahi, const bf* __restrict__ Alo,
    const bf* __restrict__ Bhi, const bf* __restrict__ Blo,
    const float* __restrict__ bias, const float* __restrict__ bm,
    const int* __restrict__ deg,
    float* __restrict__ C, bf* __restrict__ outHi, bf* __restrict__ outLo,
    int M, int Nout, int nSeg, int m0, int n0, char* smem)
{
    const int tid = threadIdx.x;
    const int lane = tid & 31, wid = tid >> 5;
    const int wm = wid & 3, wn = wid >> 2;
    const int NKB = nSeg * 16;
    const bool msg = (nSeg > 1);
    u32 sb = smem_u32(smem);

    float acc[2][8][4];
#pragma unroll
    for (int i = 0; i < 2; i++)
#pragma unroll
        for (int j = 0; j < 8; j++)
#pragma unroll
            for (int k = 0; k < 4; k++) acc[i][j][k] = 0.f;

#pragma unroll
    for (int s = 0; s < 2; s++) {
        int tseg = s >> 4, koff = (s & 15) * 32;
        size_t ao = (size_t)tseg * ((size_t)Nn * Hh) + koff;
        size_t bo = (size_t)tseg * ((size_t)Hh * Hh) + koff;
        u32 dst = sb + s * BUFSZ;
        cpa_tile2(Ahi + ao, Alo + ao, M, m0, tid, dst);
        cpa_tile2(Bhi + bo, Blo + bo, 1 << 30, n0, tid, dst + TILE_SZ);
        CPA_COMMIT();
    }

    int buf = 0;
    for (int kb = 0; kb < NKB; kb++) {
        if (kb == NKB - 1) { CPA_WAIT0(); } else { CPA_WAIT1(); }
        __syncthreads();

        if (kb + 2 < NKB) {
            int kn = kb + 2;
            int tseg = kn >> 4, koff = (kn & 15) * 32;
            size_t ao = (size_t)tseg * ((size_t)Nn * Hh) + koff;
            size_t bo = (size_t)tseg * ((size_t)Hh * Hh) + koff;
            int bn = buf + 2; if (bn >= NSTAGE) bn -= NSTAGE;
            u32 dst = sb + bn * BUFSZ;
            cpa_tile2(Ahi + ao, Alo + ao, M, m0, tid, dst);
            cpa_tile2(Bhi + bo, Blo + bo, 1 << 30, n0, tid, dst + TILE_SZ);
            CPA_COMMIT();
        }

        u32 aT = sb + buf * BUFSZ;
        u32 bT = aT + TILE_SZ;
#pragma unroll
        for (int ks = 0; ks < 2; ks++) {
            int lcA = 2 * ks + (lane >> 4);
            u32 ah[2][4], al[2][4];
#pragma unroll
            for (int mt = 0; mt < 2; mt++) {
                int row = wm * 32 + mt * 16 + (lane & 15);
                ldsm4(ah[mt], aT + tswz(row, lcA));
                ldsm4(al[mt], aT + tswz(row, lcA + 4));
            }
#pragma unroll
            for (int half = 0; half < 2; half++) {
                u32 bh[2][4], bl[2][4];
#pragma unroll
                for (int np = 0; np < 2; np++) {
                    int np2 = half * 2 + np;
                    int row = wn * 64 + np2 * 16 + (lane & 7) + ((lane >> 3) & 1) * 8;
                    ldsm4(bh[np], bT + tswz(row, lcA));
                    ldsm4(bl[np], bT + tswz(row, lcA + 4));
                }
#pragma unroll
                for (int mt = 0; mt < 2; mt++)
#pragma unroll
                    for (int j = 0; j < 4; j++) {
                        int np = j >> 1, sub = j & 1;
                        int nt = half * 4 + j;
                        mma16816(acc[mt][nt], ah[mt], bh[np][sub], bh[np][sub + 2]);
                        mma16816(acc[mt][nt], ah[mt], bl[np][sub], bl[np][sub + 2]);
                        mma16816(acc[mt][nt], al[mt], bh[np][sub], bh[np][sub + 2]);
                    }
            }
        }
        buf++; if (buf >= NSTAGE) buf = 0;
    }

    __syncthreads();

    // ---- epilogue ----
#pragma unroll
    for (int mt = 0; mt < 2; mt++) {
        int rbase = m0 + wm * 32 + mt * 16 + (lane >> 2);
#pragma unroll
        for (int half = 0; half < 2; half++) {
            int r = rbase + half * 8;
            if (r >= M) continue;
            float dgv[Tt];
            if (msg) {
#pragma unroll
                for (int t = 0; t < Tt; t++) dgv[t] = (float)deg[t * Nn + r];
            }
#pragma unroll
            for (int nt = 0; nt < 8; nt++) {
                int col = n0 + wn * 64 + nt * 8 + (lane & 3) * 2;
                float v0 = acc[mt][nt][half * 2 + 0];
                float v1 = acc[mt][nt][half * 2 + 1];
                if (msg) {
#pragma unroll
                    for (int t = 0; t < Tt; t++) {
                        float2 b = *reinterpret_cast<const float2*>(bm + t * Hh + col);
                        v0 += dgv[t] * b.x;
                        v1 += dgv[t] * b.y;
                    }
                } else {
                    float2 b = *reinterpret_cast<const float2*>(bias + col);
                    v0 += b.x; v1 += b.y;
                }
                if (outHi) {
                    bf h0, l0, h1, l1;
                    split1(v0, h0, l0);
                    split1(v1, h1, l1);
                    size_t o = (size_t)r * Nout + col;
                    *reinterpret_cast<__nv_bfloat162*>(outHi + o) = __nv_bfloat162(h0, h1);
                    *reinterpret_cast<__nv_bfloat162*>(outLo + o) = __nv_bfloat162(l0, l1);
                } else {
                    *reinterpret_cast<float2*>(C + (size_t)r * Nout + col) = make_float2(v0, v1);
                }
            }
        }
    }
}

// single-purpose GEMM (gi, fc)
__global__ __launch_bounds__(256, 2)
void mma_gemm(const bf* __restrict__ Ahi, const bf* __restrict__ Alo,
              const bf* __restrict__ Bhi, const bf* __restrict__ Blo,
              const float* __restrict__ bias, const float* __restrict__ bm,
              const int* __restrict__ deg,
              float* __restrict__ C, bf* __restrict__ outHi, bf* __restrict__ outLo,
              int M, int Nout, int nSeg)
{
    extern __shared__ __align__(16) char smem[];
    gemm_body(Ahi, Alo, Bhi, Blo, bias, bm, deg, C, outHi, outLo,
              M, Nout, nSeg, blockIdx.x * 128, blockIdx.y * 128, smem);
}

// dual launch: y<4 -> msg GEMM (long, 4xK, scheduled first), y>=4 -> gh GEMM
__global__ __launch_bounds__(256, 2)
void mma_dual(const bf* __restrict__ Shi, const bf* __restrict__ Slo,
              const bf* __restrict__ Wmh, const bf* __restrict__ Wml,
              const float* __restrict__ bm, const int* __restrict__ deg,
              bf* __restrict__ iHi, bf* __restrict__ iLo,
              const bf* __restrict__ hhi, const bf* __restrict__ hlo,
              const bf* __restrict__ Whh, const bf* __restrict__ Whl,
              const float* __restrict__ bhh, float* __restrict__ gh)
{
    extern __shared__ __align__(16) char smem[];
    int y = blockIdx.y;
    if (y < 4) {
        gemm_body(Shi, Slo, Wmh, Wml, nullptr, bm, deg,
                  nullptr, iHi, iLo, Nn, Hh, Tt,
                  blockIdx.x * 128, y * 128, smem);
    } else {
        gemm_body(hhi, hlo, Whh, Whl, bhh, nullptr, nullptr,
                  gh, nullptr, nullptr, Nn, G3, 1,
                  blockIdx.x * 128, (y - 4) * 128, smem);
    }
}

// ---------------- utility / conversion kernels ----------------
__global__ void copy_f4(const float4* __restrict__ s, float4* __restrict__ d, int n4) {
    int i = blockIdx.x * blockDim.x + threadIdx.x;
    int stride = gridDim.x * blockDim.x;
    for (; i < n4; i += stride) d[i] = s[i];
}
__global__ void cvt_split(const float* __restrict__ in, bf* __restrict__ hi,
                          bf* __restrict__ lo, int n4) {
    int i = blockIdx.x * blockDim.x + threadIdx.x;
    int stride = gridDim.x * blockDim.x;
    for (; i < n4; i += stride) {
        float4 v = reinterpret_cast<const float4*>(in)[i];
        bf h0,l0,h1,l1,h2,l2,h3,l3;
        split1(v.x, h0, l0); split1(v.y, h1, l1);
        split1(v.z, h2, l2); split1(v.w, h3, l3);
        *reinterpret_cast<__nv_bfloat162*>(hi + i*4)     = __nv_bfloat162(h0, h1);
        *reinterpret_cast<__nv_bfloat162*>(hi + i*4 + 2) = __nv_bfloat162(h2, h3);
        *reinterpret_cast<__nv_bfloat162*>(lo + i*4)     = __nv_bfloat162(l0, l1);
        *reinterpret_cast<__nv_bfloat162*>(lo + i*4 + 2) = __nv_bfloat162(l2, l3);
    }
}
__global__ void zero_i(int* p, int n) {
    int i = blockIdx.x * blockDim.x + threadIdx.x;
    if (i < n) p[i] = 0;
}
__global__ void count_deg(const int* __restrict__ edges, int* __restrict__ deg) {
    int idx = blockIdx.x * blockDim.x + threadIdx.x;
    if (idx < Tt * Ee) {
        int t = idx / Ee;
        int tgt = edges[idx * 2 + 1];
        atomicAdd(&deg[t * Nn + tgt], 1);
    }
}

// ---------------- CSR build ----------------
__global__ void scan1(const int* __restrict__ deg, int* __restrict__ off, int* __restrict__ bsum) {
    __shared__ int sm[1024];
    int t = threadIdx.x;
    int i = blockIdx.x * 1024 + t;
    int v = (i < TN) ? deg[i] : 0;
    sm[t] = v;
    __syncthreads();
    for (int d = 1; d < 1024; d <<= 1) {
        int x = (t >= d) ? sm[t - d] : 0;
        __syncthreads();
        sm[t] += x;
        __syncthreads();
    }
    if (i < TN) off[i + 1] = sm[t];
    if (t == 1023) bsum[blockIdx.x] = sm[t];
}
__global__ void scan2(const int* __restrict__ bsum, int* __restrict__ bofs, int nb) {
    __shared__ int sm[64];
    int t = threadIdx.x;
    int v = (t < nb) ? bsum[t] : 0;
    sm[t] = v;
    __syncthreads();
    for (int d = 1; d < 64; d <<= 1) {
        int x = (t >= d) ? sm[t - d] : 0;
        __syncthreads();
        sm[t] += x;
        __syncthreads();
    }
    bofs[t] = sm[t] - v;
}
__global__ void scan3(int* __restrict__ off, const int* __restrict__ bofs) {
    int i = blockIdx.x * blockDim.x + threadIdx.x;
    if (i == 0) off[0] = 0;
    if (i < TN) off[i + 1] += bofs[i >> 10];
}
__global__ void scatter_csr(const int* __restrict__ edges, const int* __restrict__ off,
                            int* __restrict__ cur, int* __restrict__ csr) {
    int idx = blockIdx.x * blockDim.x + threadIdx.x;
    if (idx >= Tt * Ee) return;
    int t = idx / Ee;
    int src = edges[idx * 2 + 0];
    int tgt = edges[idx * 2 + 1];
    int r = t * Nn + tgt;
    int p = off[r] + atomicAdd(&cur[r], 1);
    csr[p] = src;
}

// ---------------- CSR aggregation -> bf16 hi/lo S ----------------
__device__ __forceinline__ void st4_split(bf* hi, bf* lo, float4 a) {
    bf h0,l0,h1,l1,h2,l2,h3,l3;
    split1(a.x, h0, l0); split1(a.y, h1, l1);
    split1(a.z, h2, l2); split1(a.w, h3, l3);
    *reinterpret_cast<__nv_bfloat162*>(hi)     = __nv_bfloat162(h0, h1);
    *reinterpret_cast<__nv_bfloat162*>(hi + 2) = __nv_bfloat162(h2, h3);
    *reinterpret_cast<__nv_bfloat162*>(lo)     = __nv_bfloat162(l0, l1);
    *reinterpret_cast<__nv_bfloat162*>(lo + 2) = __nv_bfloat162(l2, l3);
}
__global__ void agg_csr(const float* __restrict__ h, const int* __restrict__ csr,
                        const int* __restrict__ off, bf* __restrict__ Shi,
                        bf* __restrict__ Slo) {
    int row = (blockIdx.x * blockDim.x + threadIdx.x) >> 5;
    int lane = threadIdx.x & 31;
    if (row >= TN) return;
    int s = off[row], e = off[row + 1];
    float4 a0 = make_float4(0.f,0.f,0.f,0.f), a1 = a0, a2 = a0, a3 = a0;
    for (int i = s; i < e; i++) {
        int src = __ldg(csr + i);
        const float4* hp = reinterpret_cast<const float4*>(h + (size_t)src * Hh);
        float4 v0 = hp[lane], v1 = hp[lane + 32], v2 = hp[lane + 64], v3 = hp[lane + 96];
        a0.x += v0.x; a0.y += v0.y; a0.z += v0.z; a0.w += v0.w;
        a1.x += v1.x; a1.y += v1.y; a1.z += v1.z; a1.w += v1.w;
        a2.x += v2.x; a2.y += v2.y; a2.z += v2.z; a2.w += v2.w;
        a3.x += v3.x; a3.y += v3.y; a3.z += v3.z; a3.w += v3.w;
    }
    bf* Hp = Shi + (size_t)row * Hh;
    bf* Lp = Slo + (size_t)row * Hh;
    st4_split(Hp + lane * 4,         Lp + lane * 4,         a0);
    st4_split(Hp + (lane + 32) * 4,  Lp + (lane + 32) * 4,  a1);
    st4_split(Hp + (lane + 64) * 4,  Lp + (lane + 64) * 4,  a2);
    st4_split(Hp + (lane + 96) * 4,  Lp + (lane + 96) * 4,  a3);
}

// ---------------- GRU elementwise ----------------
__global__ void gru_kernel(const float* __restrict__ gi, const float* __restrict__ gh,
                           const float* __restrict__ h, float* __restrict__ hout,
                           bf* __restrict__ hhi, bf* __restrict__ hlo) {
    int idx = blockIdx.x * blockDim.x + threadIdx.x;
    if (idx >= Nn * Hh) return;
    int n = idx / Hh;
    int j = idx - n * Hh;
    size_t base = (size_t)n * G3 + j;
    float ir = gi[base],          hr = gh[base];
    float iz = gi[base + Hh],     hz = gh[base + Hh];
    float in_ = gi[base + 2*Hh],  hn = gh[base + 2*Hh];
    float r = 1.f / (1.f + expf(-(ir + hr)));
    float z = 1.f / (1.f + expf(-(iz + hz)));
    float nv = tanhf(in_ + r * hn);
    float hv = (1.f - z) * nv + z * h[idx];
    hout[idx] = hv;
    bf hb, lb;
    split1(hv, hb, lb);
    hhi[idx] = hb;
    hlo[idx] = lb;
}

// ---------------- column max ----------------
__global__ void pmax_kernel(const float* __restrict__ X, float* __restrict__ pm) {
    int k = threadIdx.x;
    int b = blockIdx.x;
    float m = -INFINITY;
    int r0 = b * 100;
    for (int r = 0; r < 100; r++)
        m = fmaxf(m, X[(size_t)(r0 + r) * Hh + k]);
    pm[b * Hh + k] = m;
}
__global__ void fmax_kernel(const float* __restrict__ pm, float* __restrict__ out) {
    int k = threadIdx.x;
    float m = -INFINITY;
    for (int b = 0; b < 100; b++)
        m = fmaxf(m, pm[b * Hh + k]);
    out[k] = m;
}

// ---------------- launch ----------------
extern "C" void kernel_launch(void* const* d_in, const int* in_sizes, int n_in,
                              void* d_out, int out_size) {
    const float* x     = (const float*)d_in[0];
    const int*   edges = (const int*)  d_in[1];
    const float* W_msg = (const float*)d_in[2];
    const float* b_msg = (const float*)d_in[3];
    const float* W_ih  = (const float*)d_in[4];
    const float* W_hh  = (const float*)d_in[5];
    const float* b_ih  = (const float*)d_in[6];
    const float* b_hh  = (const float*)d_in[7];
    const float* fc_W  = (const float*)d_in[8];
    const float* fc_b  = (const float*)d_in[9];
    float* out = (float*)d_out;

    float *ph, *pgi, *pgh, *ppm;
    bf *pShi, *pSlo, *pihi, *pilo, *phhi, *phlo;
    bf *pWmh, *pWml, *pWih, *pWil, *pWhh, *pWhl, *pfch, *pfcl;
    int *pdeg, *poff, *pcur, *pcsr, *pbsum, *pbofs;
    cudaGetSymbolAddress((void**)&ph,    g_h);
    cudaGetSymbolAddress((void**)&pgi,   g_gi);
    cudaGetSymbolAddress((void**)&pgh,   g_gh);
    cudaGetSymbolAddress((void**)&ppm,   g_pm);
    cudaGetSymbolAddress((void**)&pShi,  g_Shi);
    cudaGetSymbolAddress((void**)&pSlo,  g_Slo);
    cudaGetSymbolAddress((void**)&pihi,  g_ihi);
    cudaGetSymbolAddress((void**)&pilo,  g_ilo);
    cudaGetSymbolAddress((void**)&phhi,  g_hhi);
    cudaGetSymbolAddress((void**)&phlo,  g_hlo);
    cudaGetSymbolAddress((void**)&pWmh,  g_Wmh);
    cudaGetSymbolAddress((void**)&pWml,  g_Wml);
    cudaGetSymbolAddress((void**)&pWih,  g_Wih);
    cudaGetSymbolAddress((void**)&pWil,  g_Wil);
    cudaGetSymbolAddress((void**)&pWhh,  g_Whh);
    cudaGetSymbolAddress((void**)&pWhl,  g_Whl);
    cudaGetSymbolAddress((void**)&pfch,  g_fch);
    cudaGetSymbolAddress((void**)&pfcl,  g_fcl);
    cudaGetSymbolAddress((void**)&pdeg,  g_deg);
    cudaGetSymbolAddress((void**)&poff,  g_off);
    cudaGetSymbolAddress((void**)&pcur,  g_cur);
    cudaGetSymbolAddress((void**)&pcsr,  g_csr);
    cudaGetSymbolAddress((void**)&pbsum, g_bsum);
    cudaGetSymbolAddress((void**)&pbofs, g_bofs);

    cudaFuncSetAttribute(mma_gemm, cudaFuncAttributeMaxDynamicSharedMemorySize, SMEM_BYTES);
    cudaFuncSetAttribute(mma_dual, cudaFuncAttributeMaxDynamicSharedMemorySize, SMEM_BYTES);

    float* hc = ph;
    float* hn = ph + (size_t)Nn * Hh;

    copy_f4<<<2048, 256>>>((const float4*)x, (float4*)hc, Nn * Hh / 4);
    cvt_split<<<2048, 256>>>(x, phhi, phlo, Nn * Hh / 4);
    cvt_split<<<2048, 256>>>(W_msg, pWmh, pWml, WMSG_SZ / 4);
    cvt_split<<<2048, 256>>>(W_ih,  pWih, pWil, WIH_SZ / 4);
    cvt_split<<<2048, 256>>>(W_hh,  pWhh, pWhl, WIH_SZ / 4);
    cvt_split<<<1024, 256>>>(fc_W,  pfch, pfcl, FC_SZ / 4);

    zero_i<<<(TN + 255) / 256, 256>>>(pdeg, TN);
    zero_i<<<(TN + 255) / 256, 256>>>(pcur, TN);
    count_deg<<<(Tt * Ee + 255) / 256, 256>>>(edges, pdeg);
    scan1<<<(TN + 1023) / 1024, 1024>>>(pdeg, poff, pbsum);
    scan2<<<1, 64>>>(pbsum, pbofs, (TN + 1023) / 1024);
    scan3<<<(TN + 255) / 256, 256>>>(poff, pbofs);
    scatter_csr<<<(Tt * Ee + 255) / 256, 256>>>(edges, poff, pcur, pcsr);

    dim3 gm((Nn + 127) / 128, Hh / 128);    // 79 x 4  (fc)
    dim3 gd((Nn + 127) / 128, 16);          // 79 x 16 (msg + gh dual)
    dim3 gg((Nn + 127) / 128, G3 / 128);    // 79 x 12 (gi)
    int aggBlocks = (TN * 32 + 255) / 256;

    for (int layer = 0; layer < Ll; layer++) {
        const bf* Wmh_l = pWmh + (size_t)layer * Tt * Hh * Hh;
        const bf* Wml_l = pWml + (size_t)layer * Tt * Hh * Hh;
        const bf* Wih_l = pWih + (size_t)layer * G3 * Hh;
        const bf* Wil_l = pWil + (size_t)layer * G3 * Hh;
        const bf* Whh_l = pWhh + (size_t)layer * G3 * Hh;
        const bf* Whl_l = pWhl + (size_t)layer * G3 * Hh;
        const float* bm_l  = b_msg + (size_t)layer * Tt * Hh;
        const float* bih_l = b_ih  + (size_t)layer * G3;
        const float* bhh_l = b_hh  + (size_t)layer * G3;
        for (int s = 0; s < 2; s++) {
            agg_csr<<<aggBlocks, 256>>>(hc, pcsr, poff, pShi, pSlo);
            // msg GEMM (long CTAs first) + gh GEMM co-scheduled in one launch
            mma_dual<<<gd, 256, SMEM_BYTES>>>(pShi, pSlo, Wmh_l, Wml_l, bm_l, pdeg,
                                              pihi, pilo,
                                              phhi, phlo, Whh_l, Whl_l, bhh_l, pgh);
            mma_gemm<<<gg, 256, SMEM_BYTES>>>(pihi, pilo, Wih_l, Wil_l,
                                              bih_l, nullptr, nullptr,
                                              pgi, nullptr, nullptr, Nn, G3, 1);
            gru_kernel<<<(Nn * Hh + 255) / 256, 256>>>(pgi, pgh, hc, hn, phhi, phlo);
            float* t = hc; hc = hn; hn = t;
        }
    }

    mma_gemm<<<gm, 256, SMEM_BYTES>>>(phhi, phlo, pfch, pfcl,
                                      fc_b, nullptr, nullptr,
                                      pgi, nullptr, nullptr, Nn, Hh, 1);
    pmax_kernel<<<100, 512>>>(pgi, ppm);
    fmax_kernel<<<1, 512>>>(ppm, out);
}

// round 10
// speedup vs baseline: 1.4623x; 1.0471x over previous
#include <cuda_runtime.h>
#include <cuda_bf16.h>
#include <math.h>

#define Nn 10000
#define Hh 512
#define Tt 4
#define Ee 40000
#define Ll 2
#define G3 (3*Hh)
#define TN (Tt*Nn)
#define WMSG_SZ (Ll*Tt*Hh*Hh)
#define WIH_SZ  (Ll*G3*Hh)
#define FC_SZ   (Hh*Hh)

typedef unsigned long long u64;
typedef unsigned int u32;
typedef __nv_bfloat16 bf;

// ---------------- device scratch ----------------
__device__ __align__(16) float g_h  [2*(size_t)Nn*Hh];
__device__ __align__(16) float g_gi [(size_t)Nn*G3];
__device__ __align__(16) float g_gh [(size_t)Nn*G3];
__device__ __align__(16) float g_pm [100*Hh];
__device__ __align__(16) bf g_Shi[(size_t)TN*Hh];
__device__ __align__(16) bf g_Slo[(size_t)TN*Hh];
__device__ __align__(16) bf g_ihi[(size_t)Nn*Hh];
__device__ __align__(16) bf g_ilo[(size_t)Nn*Hh];
__device__ __align__(16) bf g_hhi[(size_t)Nn*Hh];
__device__ __align__(16) bf g_hlo[(size_t)Nn*Hh];
__device__ __align__(16) bf g_Wmh[WMSG_SZ];
__device__ __align__(16) bf g_Wml[WMSG_SZ];
__device__ __align__(16) bf g_Wih[WIH_SZ];
__device__ __align__(16) bf g_Wil[WIH_SZ];
__device__ __align__(16) bf g_Whh[WIH_SZ];
__device__ __align__(16) bf g_Whl[WIH_SZ];
__device__ __align__(16) bf g_fch[FC_SZ];
__device__ __align__(16) bf g_fcl[FC_SZ];
__device__ int g_deg [TN];
__device__ int g_off [TN + 1];
__device__ int g_cur [TN];
__device__ int g_csr [Tt*Ee];
__device__ int g_bsum[64];
__device__ int g_bofs[64];

// ---------------- smem geometry: interleaved hi/lo, 128B swizzled rows ----------------
#define TILE_SZ 16384
#define BUFSZ   (2*TILE_SZ)
#define NSTAGE  3
#define SMEM_BYTES (NSTAGE*BUFSZ)   // 98304

__device__ __forceinline__ u32 smem_u32(const void* p) {
    u32 a;
    asm("{ .reg .u64 t; cvta.to.shared.u64 t, %1; cvt.u32.u64 %0, t; }" : "=r"(a) : "l"(p));
    return a;
}
__device__ __forceinline__ void ldsm4(u32 r[4], u32 addr) {
    asm volatile("ldmatrix.sync.aligned.m8n8.x4.shared.b16 {%0,%1,%2,%3}, [%4];"
                 : "=r"(r[0]), "=r"(r[1]), "=r"(r[2]), "=r"(r[3]) : "r"(addr));
}
__device__ __forceinline__ void mma16816(float d[4], const u32 a[4], u32 b0, u32 b1) {
    asm volatile("mma.sync.aligned.m16n8k16.row.col.f32.bf16.bf16.f32 "
                 "{%0,%1,%2,%3}, {%4,%5,%6,%7}, {%8,%9}, {%0,%1,%2,%3};"
                 : "+f"(d[0]), "+f"(d[1]), "+f"(d[2]), "+f"(d[3])
                 : "r"(a[0]), "r"(a[1]), "r"(a[2]), "r"(a[3]), "r"(b0), "r"(b1));
}
__device__ __forceinline__ void split1(float v, bf& h, bf& l) {
    h = __float2bfloat16(v);
    l = __float2bfloat16(v - __bfloat162float(h));
}
__device__ __forceinline__ void cpa16(u32 saddr, const void* g) {
    asm volatile("cp.async.cg.shared.global [%0], [%1], 16;" :: "r"(saddr), "l"(g) : "memory");
}
#define CPA_COMMIT() asm volatile("cp.async.commit_group;" ::: "memory")
#define CPA_WAIT1()  asm volatile("cp.async.wait_group 1;" ::: "memory")

__device__ __forceinline__ u32 tswz(int row, int lc) {
    return (u32)(row * 128 + ((lc ^ (row & 7)) << 4));
}

__device__ __forceinline__ void cpa_tile2(const bf* __restrict__ hi, const bf* __restrict__ lo,
                                          int rowMax, int r0, int tid, u32 sdst) {
#pragma unroll
    for (int i = 0; i < 4; i++) {
        int c = i * 256 + tid;
        int row = c >> 3;
        int lc  = c & 7;
        int m = r0 + row;
        if (m >= rowMax) m = rowMax - 1;
        const bf* src = (lc < 4) ? hi + (size_t)m * Hh + lc * 8
                                 : lo + (size_t)m * Hh + (lc - 4) * 8;
        cpa16(sdst + tswz(row, lc), src);
    }
}

// ============ shared GEMM body: bf16 3-split HMMA, 3-stage cp.async ============
__device__ __forceinline__ void gemm_body(
    const bf* __restrict__ Ahi, const bf* __restrict__ Alo,
    const bf* __restrict__ Bhi, const bf* __restrict__ Blo,
    const float* __restrict__ bias, const float* __restrict__ bm,
    const int* __restrict__ deg,
    float* __restrict__ C, bf* __restrict__ outHi, bf* __restrict__ outLo,
    int M, int Nout, int nSeg, int m0, int n0, char* smem)
{
    const int tid = threadIdx.x;
    const int lane = tid & 31, wid = tid >> 5;
    const int wm = wid & 3, wn = wid >> 2;
    const int NKB = nSeg * 16;
    const bool msg = (nSeg > 1);
    u32 sb = smem_u32(smem);

    float acc[2][8][4];
#pragma unroll
    for (int i = 0; i < 2; i++)
#pragma unroll
        for (int j = 0; j < 8; j++)
#pragma unroll
            for (int k = 0; k < 4; k++) acc[i][j][k] = 0.f;

#pragma unroll
    for (int s = 0; s < 2; s++) {
        int tseg = s >> 4, koff = (s & 15) * 32;
        size_t ao = (size_t)tseg * ((size_t)Nn * Hh) + koff;
        size_t bo = (size_t)tseg * ((size_t)Hh * Hh) + koff;
        u32 dst = sb + s * BUFSZ;
        cpa_tile2(Ahi + ao, Alo + ao, M, m0, tid, dst);
        cpa_tile2(Bhi + bo, Blo + bo, 1 << 30, n0, tid, dst + TILE_SZ);
        CPA_COMMIT();
    }

    int buf = 0;
    for (int kb = 0; kb < NKB; kb++) {
        CPA_WAIT1();
        __syncthreads();

        if (kb + 2 < NKB) {
            int kn = kb + 2;
            int tseg = kn >> 4, koff = (kn & 15) * 32;
            size_t ao = (size_t)tseg * ((size_t)Nn * Hh) + koff;
            size_t bo = (size_t)tseg * ((size_t)Hh * Hh) + koff;
            int bn = buf + 2; if (bn >= NSTAGE) bn -= NSTAGE;
            u32 dst = sb + bn * BUFSZ;
            cpa_tile2(Ahi + ao, Alo + ao, M, m0, tid, dst);
            cpa_tile2(Bhi + bo, Blo + bo, 1 << 30, n0, tid, dst + TILE_SZ);
        }
        CPA_COMMIT();   // empty group near the end keeps WAIT1 semantics uniform

        u32 aT = sb + buf * BUFSZ;
        u32 bT = aT + TILE_SZ;
#pragma unroll
        for (int ks = 0; ks < 2; ks++) {
            int lcA = 2 * ks + (lane >> 4);
            u32 ah[2][4], al[2][4];
#pragma unroll
            for (int mt = 0; mt < 2; mt++) {
                int row = wm * 32 + mt * 16 + (lane & 15);
                ldsm4(ah[mt], aT + tswz(row, lcA));
                ldsm4(al[mt], aT + tswz(row, lcA + 4));
            }
#pragma unroll
            for (int half = 0; half < 2; half++) {
                u32 bh[2][4], bl[2][4];
#pragma unroll
                for (int np = 0; np < 2; np++) {
                    int np2 = half * 2 + np;
                    int row = wn * 64 + np2 * 16 + (lane & 7) + ((lane >> 3) & 1) * 8;
                    ldsm4(bh[np], bT + tswz(row, lcA));
                    ldsm4(bl[np], bT + tswz(row, lcA + 4));
                }
#pragma unroll
                for (int mt = 0; mt < 2; mt++)
#pragma unroll
                    for (int j = 0; j < 4; j++) {
                        int np = j >> 1, sub = j & 1;
                        int nt = half * 4 + j;
                        mma16816(acc[mt][nt], ah[mt], bh[np][sub], bh[np][sub + 2]);
                        mma16816(acc[mt][nt], ah[mt], bl[np][sub], bl[np][sub + 2]);
                        mma16816(acc[mt][nt], al[mt], bh[np][sub], bh[np][sub + 2]);
                    }
            }
        }
        buf++; if (buf >= NSTAGE) buf = 0;
    }

    __syncthreads();

    // ---- epilogue ----
#pragma unroll
    for (int mt = 0; mt < 2; mt++) {
        int rbase = m0 + wm * 32 + mt * 16 + (lane >> 2);
#pragma unroll
        for (int half = 0; half < 2; half++) {
            int r = rbase + half * 8;
            if (r >= M) continue;
            float dgv[Tt];
            if (msg) {
#pragma unroll
                for (int t = 0; t < Tt; t++) dgv[t] = (float)deg[t * Nn + r];
            }
#pragma unroll
            for (int nt = 0; nt < 8; nt++) {
                int col = n0 + wn * 64 + nt * 8 + (lane & 3) * 2;
                float v0 = acc[mt][nt][half * 2 + 0];
                float v1 = acc[mt][nt][half * 2 + 1];
                if (msg) {
#pragma unroll
                    for (int t = 0; t < Tt; t++) {
                        float2 b = *reinterpret_cast<const float2*>(bm + t * Hh + col);
                        v0 += dgv[t] * b.x;
                        v1 += dgv[t] * b.y;
                    }
                } else {
                    float2 b = *reinterpret_cast<const float2*>(bias + col);
                    v0 += b.x; v1 += b.y;
                }
                if (outHi) {
                    bf h0, l0, h1, l1;
                    split1(v0, h0, l0);
                    split1(v1, h1, l1);
                    size_t o = (size_t)r * Nout + col;
                    *reinterpret_cast<__nv_bfloat162*>(outHi + o) = __nv_bfloat162(h0, h1);
                    *reinterpret_cast<__nv_bfloat162*>(outLo + o) = __nv_bfloat162(l0, l1);
                } else {
                    *reinterpret_cast<float2*>(C + (size_t)r * Nout + col) = make_float2(v0, v1);
                }
            }
        }
    }
}

// single-purpose GEMM (gi, fc)
__global__ __launch_bounds__(256, 2)
void mma_gemm(const bf* __restrict__ Ahi, const bf* __restrict__ Alo,
              const bf* __restrict__ Bhi, const bf* __restrict__ Blo,
              const float* __restrict__ bias, const float* __restrict__ bm,
              const int* __restrict__ deg,
              float* __restrict__ C, bf* __restrict__ outHi, bf* __restrict__ outLo,
              int M, int Nout, int nSeg)
{
    extern __shared__ __align__(16) char smem[];
    gemm_body(Ahi, Alo, Bhi, Blo, bias, bm, deg, C, outHi, outLo,
              M, Nout, nSeg, blockIdx.x * 128, blockIdx.y * 128, smem);
}

// dual launch: y<4 -> msg GEMM (long, 4xK, scheduled first), y>=4 -> gh GEMM
__global__ __launch_bounds__(256, 2)
void mma_dual(const bf* __restrict__ Shi, const bf* __restrict__ Slo,
              const bf* __restrict__ Wmh, const bf* __restrict__ Wml,
              const float* __restrict__ bm, const int* __restrict__ deg,
              bf* __restrict__ iHi, bf* __restrict__ iLo,
              const bf* __restrict__ hhi, const bf* __restrict__ hlo,
              const bf* __restrict__ Whh, const bf* __restrict__ Whl,
              const float* __restrict__ bhh, float* __restrict__ gh)
{
    extern __shared__ __align__(16) char smem[];
    int y = blockIdx.y;
    if (y < 4) {
        gemm_body(Shi, Slo, Wmh, Wml, nullptr, bm, deg,
                  nullptr, iHi, iLo, Nn, Hh, Tt,
                  blockIdx.x * 128, y * 128, smem);
    } else {
        gemm_body(hhi, hlo, Whh, Whl, bhh, nullptr, nullptr,
                  gh, nullptr, nullptr, Nn, G3, 1,
                  blockIdx.x * 128, (y - 4) * 128, smem);
    }
}

// ---------------- fused init: copy h=x and all bf16 splits in ONE kernel ----------------
__global__ void init_all(const float* __restrict__ x,
                         const float* __restrict__ W_msg, const float* __restrict__ W_ih,
                         const float* __restrict__ W_hh,  const float* __restrict__ fc_W,
                         float* __restrict__ h,
                         bf* __restrict__ hhi, bf* __restrict__ hlo,
                         bf* __restrict__ Wmh, bf* __restrict__ Wml,
                         bf* __restrict__ Wih, bf* __restrict__ Wil,
                         bf* __restrict__ Whh, bf* __restrict__ Whl,
                         bf* __restrict__ fch, bf* __restrict__ fcl) {
    const int R0 = Nn * Hh / 4;
    const int R1 = R0 + WMSG_SZ / 4;
    const int R2 = R1 + WIH_SZ / 4;
    const int R3 = R2 + WIH_SZ / 4;
    const int R4 = R3 + FC_SZ / 4;
    int i = blockIdx.x * blockDim.x + threadIdx.x;
    int stride = gridDim.x * blockDim.x;
    for (; i < R4; i += stride) {
        const float* src; bf* hi; bf* lo; int k; bool cp = false;
        if (i < R0)      { src = x;     hi = hhi; lo = hlo; k = i;      cp = true; }
        else if (i < R1) { src = W_msg; hi = Wmh; lo = Wml; k = i - R0; }
        else if (i < R2) { src = W_ih;  hi = Wih; lo = Wil; k = i - R1; }
        else if (i < R3) { src = W_hh;  hi = Whh; lo = Whl; k = i - R2; }
        else             { src = fc_W;  hi = fch; lo = fcl; k = i - R3; }
        float4 v = reinterpret_cast<const float4*>(src)[k];
        if (cp) reinterpret_cast<float4*>(h)[k] = v;
        bf h0,l0,h1,l1,h2,l2,h3,l3;
        split1(v.x, h0, l0); split1(v.y, h1, l1);
        split1(v.z, h2, l2); split1(v.w, h3, l3);
        *reinterpret_cast<__nv_bfloat162*>(hi + k*4)     = __nv_bfloat162(h0, h1);
        *reinterpret_cast<__nv_bfloat162*>(hi + k*4 + 2) = __nv_bfloat162(h2, h3);
        *reinterpret_cast<__nv_bfloat162*>(lo + k*4)     = __nv_bfloat162(l0, l1);
        *reinterpret_cast<__nv_bfloat162*>(lo + k*4 + 2) = __nv_bfloat162(l2, l3);
    }
}

__global__ void zero2_i(int* p, int* q, int n) {
    int i = blockIdx.x * blockDim.x + threadIdx.x;
    if (i < n) { p[i] = 0; q[i] = 0; }
}
__global__ void count_deg(const int* __restrict__ edges, int* __restrict__ deg) {
    int idx = blockIdx.x * blockDim.x + threadIdx.x;
    if (idx < Tt * Ee) {
        int t = idx / Ee;
        int tgt = edges[idx * 2 + 1];
        atomicAdd(&deg[t * Nn + tgt], 1);
    }
}

// ---------------- CSR build ----------------
__global__ void scan1(const int* __restrict__ deg, int* __restrict__ off, int* __restrict__ bsum) {
    __shared__ int sm[1024];
    int t = threadIdx.x;
    int i = blockIdx.x * 1024 + t;
    int v = (i < TN) ? deg[i] : 0;
    sm[t] = v;
    __syncthreads();
    for (int d = 1; d < 1024; d <<= 1) {
        int x = (t >= d) ? sm[t - d] : 0;
        __syncthreads();
        sm[t] += x;
        __syncthreads();
    }
    if (i < TN) off[i + 1] = sm[t];
    if (t == 1023) bsum[blockIdx.x] = sm[t];
}
__global__ void scan2(const int* __restrict__ bsum, int* __restrict__ bofs, int nb) {
    __shared__ int sm[64];
    int t = threadIdx.x;
    int v = (t < nb) ? bsum[t] : 0;
    sm[t] = v;
    __syncthreads();
    for (int d = 1; d < 64; d <<= 1) {
        int x = (t >= d) ? sm[t - d] : 0;
        __syncthreads();
        sm[t] += x;
        __syncthreads();
    }
    bofs[t] = sm[t] - v;
}
__global__ void scan3(int* __restrict__ off, const int* __restrict__ bofs) {
    int i = blockIdx.x * blockDim.x + threadIdx.x;
    if (i == 0) off[0] = 0;
    if (i < TN) off[i + 1] += bofs[i >> 10];
}
__global__ void scatter_csr(const int* __restrict__ edges, const int* __restrict__ off,
                            int* __restrict__ cur, int* __restrict__ csr) {
    int idx = blockIdx.x * blockDim.x + threadIdx.x;
    if (idx >= Tt * Ee) return;
    int t = idx / Ee;
    int src = edges[idx * 2 + 0];
    int tgt = edges[idx * 2 + 1];
    int r = t * Nn + tgt;
    int p = off[r] + atomicAdd(&cur[r], 1);
    csr[p] = src;
}

// ---------------- CSR aggregation -> bf16 hi/lo S (2-edge unroll for MLP) ----------------
__device__ __forceinline__ void st4_split(bf* hi, bf* lo, float4 a) {
    bf h0,l0,h1,l1,h2,l2,h3,l3;
    split1(a.x, h0, l0); split1(a.y, h1, l1);
    split1(a.z, h2, l2); split1(a.w, h3, l3);
    *reinterpret_cast<__nv_bfloat162*>(hi)     = __nv_bfloat162(h0, h1);
    *reinterpret_cast<__nv_bfloat162*>(hi + 2) = __nv_bfloat162(h2, h3);
    *reinterpret_cast<__nv_bfloat162*>(lo)     = __nv_bfloat162(l0, l1);
    *reinterpret_cast<__nv_bfloat162*>(lo + 2) = __nv_bfloat162(l2, l3);
}
__device__ __forceinline__ void acc4(float4& a, float4 v) {
    a.x += v.x; a.y += v.y; a.z += v.z; a.w += v.w;
}
__global__ void agg_csr(const float* __restrict__ h, const int* __restrict__ csr,
                        const int* __restrict__ off, bf* __restrict__ Shi,
                        bf* __restrict__ Slo) {
    int row = (blockIdx.x * blockDim.x + threadIdx.x) >> 5;
    int lane = threadIdx.x & 31;
    if (row >= TN) return;
    int s = off[row], e = off[row + 1];
    float4 a0 = make_float4(0.f,0.f,0.f,0.f), a1 = a0, a2 = a0, a3 = a0;
    int i = s;
    for (; i + 2 <= e; i += 2) {
        int s0 = __ldg(csr + i), s1 = __ldg(csr + i + 1);
        const float4* p0 = reinterpret_cast<const float4*>(h + (size_t)s0 * Hh);
        const float4* p1 = reinterpret_cast<const float4*>(h + (size_t)s1 * Hh);
        float4 u0 = p0[lane],      w0 = p1[lane];
        float4 u1 = p0[lane + 32], w1 = p1[lane + 32];
        float4 u2 = p0[lane + 64], w2 = p1[lane + 64];
        float4 u3 = p0[lane + 96], w3 = p1[lane + 96];
        acc4(a0, u0); acc4(a0, w0);
        acc4(a1, u1); acc4(a1, w1);
        acc4(a2, u2); acc4(a2, w2);
        acc4(a3, u3); acc4(a3, w3);
    }
    if (i < e) {
        int s0 = __ldg(csr + i);
        const float4* p0 = reinterpret_cast<const float4*>(h + (size_t)s0 * Hh);
        acc4(a0, p0[lane]); acc4(a1, p0[lane + 32]);
        acc4(a2, p0[lane + 64]); acc4(a3, p0[lane + 96]);
    }
    bf* Hp = Shi + (size_t)row * Hh;
    bf* Lp = Slo + (size_t)row * Hh;
    st4_split(Hp + lane * 4,         Lp + lane * 4,         a0);
    st4_split(Hp + (lane + 32) * 4,  Lp + (lane + 32) * 4,  a1);
    st4_split(Hp + (lane + 64) * 4,  Lp + (lane + 64) * 4,  a2);
    st4_split(Hp + (lane + 96) * 4,  Lp + (lane + 96) * 4,  a3);
}

// ---------------- GRU elementwise, float4 vectorized ----------------
__global__ void gru_kernel(const float* __restrict__ gi, const float* __restrict__ gh,
                           const float* __restrict__ h, float* __restrict__ hout,
                           bf* __restrict__ hhi, bf* __restrict__ hlo) {
    int idx4 = blockIdx.x * blockDim.x + threadIdx.x;
    if (idx4 >= Nn * Hh / 4) return;
    int n = idx4 >> 7;             // / (Hh/4)
    int j4 = idx4 & 127;
    size_t base = ((size_t)n * G3 + j4 * 4) >> 2;   // float4 index
    const float4* gi4 = reinterpret_cast<const float4*>(gi);
    const float4* gh4 = reinterpret_cast<const float4*>(gh);
    float4 ir = gi4[base],        hr = gh4[base];
    float4 iz = gi4[base + 128],  hz = gh4[base + 128];
    float4 in_ = gi4[base + 256], hn = gh4[base + 256];
    float4 hv = reinterpret_cast<const float4*>(h)[idx4];
    float o[4];
    float irA[4] = {ir.x, ir.y, ir.z, ir.w}, hrA[4] = {hr.x, hr.y, hr.z, hr.w};
    float izA[4] = {iz.x, iz.y, iz.z, iz.w}, hzA[4] = {hz.x, hz.y, hz.z, hz.w};
    float inA[4] = {in_.x, in_.y, in_.z, in_.w}, hnA[4] = {hn.x, hn.y, hn.z, hn.w};
    float hA[4]  = {hv.x, hv.y, hv.z, hv.w};
#pragma unroll
    for (int q = 0; q < 4; q++) {
        float r = 1.f / (1.f + expf(-(irA[q] + hrA[q])));
        float z = 1.f / (1.f + expf(-(izA[q] + hzA[q])));
        float nv = tanhf(inA[q] + r * hnA[q]);
        o[q] = (1.f - z) * nv + z * hA[q];
    }
    reinterpret_cast<float4*>(hout)[idx4] = make_float4(o[0], o[1], o[2], o[3]);
    bf h0,l0,h1,l1,h2,l2,h3,l3;
    split1(o[0], h0, l0); split1(o[1], h1, l1);
    split1(o[2], h2, l2); split1(o[3], h3, l3);
    *reinterpret_cast<__nv_bfloat162*>(hhi + idx4*4)     = __nv_bfloat162(h0, h1);
    *reinterpret_cast<__nv_bfloat162*>(hhi + idx4*4 + 2) = __nv_bfloat162(h2, h3);
    *reinterpret_cast<__nv_bfloat162*>(hlo + idx4*4)     = __nv_bfloat162(l0, l1);
    *reinterpret_cast<__nv_bfloat162*>(hlo + idx4*4 + 2) = __nv_bfloat162(l2, l3);
}

// ---------------- column max ----------------
__global__ void pmax_kernel(const float* __restrict__ X, float* __restrict__ pm) {
    int k = threadIdx.x;
    int b = blockIdx.x;
    float m = -INFINITY;
    int r0 = b * 100;
    for (int r = 0; r < 100; r++)
        m = fmaxf(m, X[(size_t)(r0 + r) * Hh + k]);
    pm[b * Hh + k] = m;
}
__global__ void fmax_kernel(const float* __restrict__ pm, float* __restrict__ out) {
    int k = threadIdx.x;
    float m = -INFINITY;
    for (int b = 0; b < 100; b++)
        m = fmaxf(m, pm[b * Hh + k]);
    out[k] = m;
}

// ---------------- launch ----------------
extern "C" void kernel_launch(void* const* d_in, const int* in_sizes, int n_in,
                              void* d_out, int out_size) {
    const float* x     = (const float*)d_in[0];
    const int*   edges = (const int*)  d_in[1];
    const float* W_msg = (const float*)d_in[2];
    const float* b_msg = (const float*)d_in[3];
    const float* W_ih  = (const float*)d_in[4];
    const float* W_hh  = (const float*)d_in[5];
    const float* b_ih  = (const float*)d_in[6];
    const float* b_hh  = (const float*)d_in[7];
    const float* fc_W  = (const float*)d_in[8];
    const float* fc_b  = (const float*)d_in[9];
    float* out = (float*)d_out;

    float *ph, *pgi, *pgh, *ppm;
    bf *pShi, *pSlo, *pihi, *pilo, *phhi, *phlo;
    bf *pWmh, *pWml, *pWih, *pWil, *pWhh, *pWhl, *pfch, *pfcl;
    int *pdeg, *poff, *pcur, *pcsr, *pbsum, *pbofs;
    cudaGetSymbolAddress((void**)&ph,    g_h);
    cudaGetSymbolAddress((void**)&pgi,   g_gi);
    cudaGetSymbolAddress((void**)&pgh,   g_gh);
    cudaGetSymbolAddress((void**)&ppm,   g_pm);
    cudaGetSymbolAddress((void**)&pShi,  g_Shi);
    cudaGetSymbolAddress((void**)&pSlo,  g_Slo);
    cudaGetSymbolAddress((void**)&pihi,  g_ihi);
    cudaGetSymbolAddress((void**)&pilo,  g_ilo);
    cudaGetSymbolAddress((void**)&phhi,  g_hhi);
    cudaGetSymbolAddress((void**)&phlo,  g_hlo);
    cudaGetSymbolAddress((void**)&pWmh,  g_Wmh);
    cudaGetSymbolAddress((void**)&pWml,  g_Wml);
    cudaGetSymbolAddress((void**)&pWih,  g_Wih);
    cudaGetSymbolAddress((void**)&pWil,  g_Wil);
    cudaGetSymbolAddress((void**)&pWhh,  g_Whh);
    cudaGetSymbolAddress((void**)&pWhl,  g_Whl);
    cudaGetSymbolAddress((void**)&pfch,  g_fch);
    cudaGetSymbolAddress((void**)&pfcl,  g_fcl);
    cudaGetSymbolAddress((void**)&pdeg,  g_deg);
    cudaGetSymbolAddress((void**)&poff,  g_off);
    cudaGetSymbolAddress((void**)&pcur,  g_cur);
    cudaGetSymbolAddress((void**)&pcsr,  g_csr);
    cudaGetSymbolAddress((void**)&pbsum, g_bsum);
    cudaGetSymbolAddress((void**)&pbofs, g_bofs);

    cudaFuncSetAttribute(mma_gemm, cudaFuncAttributeMaxDynamicSharedMemorySize, SMEM_BYTES);
    cudaFuncSetAttribute(mma_dual, cudaFuncAttributeMaxDynamicSharedMemorySize, SMEM_BYTES);

    float* hc = ph;
    float* hn = ph + (size_t)Nn * Hh;

    // fused init: h=x, all bf16 weight/state splits (one launch)
    init_all<<<4096, 256>>>(x, W_msg, W_ih, W_hh, fc_W, hc,
                            phhi, phlo, pWmh, pWml, pWih, pWil, pWhh, pWhl, pfch, pfcl);

    zero2_i<<<(TN + 255) / 256, 256>>>(pdeg, pcur, TN);
    count_deg<<<(Tt * Ee + 255) / 256, 256>>>(edges, pdeg);
    scan1<<<(TN + 1023) / 1024, 1024>>>(pdeg, poff, pbsum);
    scan2<<<1, 64>>>(pbsum, pbofs, (TN + 1023) / 1024);
    scan3<<<(TN + 255) / 256, 256>>>(poff, pbofs);
    scatter_csr<<<(Tt * Ee + 255) / 256, 256>>>(edges, poff, pcur, pcsr);

    dim3 gm((Nn + 127) / 128, Hh / 128);    // 79 x 4  (fc)
    dim3 gd((Nn + 127) / 128, 16);          // 79 x 16 (msg + gh dual)
    dim3 gg((Nn + 127) / 128, G3 / 128);    // 79 x 12 (gi)
    int aggBlocks = (TN * 32 + 255) / 256;

    for (int layer = 0; layer < Ll; layer++) {
        const bf* Wmh_l = pWmh + (size_t)layer * Tt * Hh * Hh;
        const bf* Wml_l = pWml + (size_t)layer * Tt * Hh * Hh;
        const bf* Wih_l = pWih + (size_t)layer * G3 * Hh;
        const bf* Wil_l = pWil + (size_t)layer * G3 * Hh;
        const bf* Whh_l = pWhh + (size_t)layer * G3 * Hh;
        const bf* Whl_l = pWhl + (size_t)layer * G3 * Hh;
        const float* bm_l  = b_msg + (size_t)layer * Tt * Hh;
        const float* bih_l = b_ih  + (size_t)layer * G3;
        const float* bhh_l = b_hh  + (size_t)layer * G3;
        for (int s = 0; s < 2; s++) {
            agg_csr<<<aggBlocks, 256>>>(hc, pcsr, poff, pShi, pSlo);
            mma_dual<<<gd, 256, SMEM_BYTES>>>(pShi, pSlo, Wmh_l, Wml_l, bm_l, pdeg,
                                              pihi, pilo,
                                              phhi, phlo, Whh_l, Whl_l, bhh_l, pgh);
            mma_gemm<<<gg, 256, SMEM_BYTES>>>(pihi, pilo, Wih_l, Wil_l,
                                              bih_l, nullptr, nullptr,
                                              pgi, nullptr, nullptr, Nn, G3, 1);
            gru_kernel<<<(Nn * Hh / 4 + 255) / 256, 256>>>(pgi, pgh, hc, hn, phhi, phlo);
            float* t = hc; hc = hn; hn = t;
        }
    }

    mma_gemm<<<gm, 256, SMEM_BYTES>>>(phhi, phlo, pfch, pfcl,
                                      fc_b, nullptr, nullptr,
                                      pgi, nullptr, nullptr, Nn, Hh, 1);
    pmax_kernel<<<100, 512>>>(pgi, ppm);
    fmax_kernel<<<1, 512>>>(ppm, out);
}